// round 11
// baseline (speedup 1.0000x reference)
#include <cuda_runtime.h>
#include <cuda_bf16.h>
#include <math.h>
#include <stdint.h>

#define BB 4
#define CC 64
#define HH 192
#define WW 192
#define NN (HH*WW)          // 36864
#define PP (BB*NN)
#define NHEADS 2

// ---------------- scratch ----------------
__device__ float g_t0[BB*CC*NN];
__device__ float g_t1[BB*CC*NN];
__device__ float g_x1[BB*CC*NN];
__device__ float g_q [BB*CC*NN];
__device__ float g_k [BB*CC*NN];
__device__ float g_v [BB*CC*NN];
__device__ float g_o1[BB*CC*NN];
__device__ float g_o2[BB*CC*NN];
__device__ float g_o3[BB*CC*NN];
__device__ float g_norm[2*BB*CC];
__device__ float g_attn[BB*NHEADS*32*32];
__device__ float g_wc[BB*3*CC*CC];     // per-batch folded weights: [b][{W1,Wrv,Wcv}][64][64]

__device__ __forceinline__ float gelu_f(float v){
    return 0.5f*v*(1.f+erff(v*0.70710678118654752f));
}
// pack two floats as bf16x2: 'lo' -> low 16 bits (even k), 'hi' -> high 16 bits (odd k)
__device__ __forceinline__ uint32_t packbf(float lo, float hi){
    uint32_t r; asm("cvt.rn.bf16x2.f32 %0, %1, %2;" : "=r"(r) : "f"(hi), "f"(lo)); return r;
}
__device__ __forceinline__ float bfhi(float v){
    return __bfloat162float(__float2bfloat16(v));
}
__device__ __forceinline__ void mma16(float* d, const uint32_t* a, uint32_t b0, uint32_t b1){
    asm("mma.sync.aligned.m16n8k16.row.col.f32.bf16.bf16.f32 "
        "{%0,%1,%2,%3},{%4,%5,%6,%7},{%8,%9},{%0,%1,%2,%3};"
        : "+f"(d[0]),"+f"(d[1]),"+f"(d[2]),"+f"(d[3])
        : "r"(a[0]),"r"(a[1]),"r"(a[2]),"r"(a[3]),"r"(b0),"r"(b1));
}
__device__ __forceinline__ void stage_pair4(uint32_t* hp, uint32_t* lp, float4 a, float4 b){
    uint4 h, l;
    h.x=packbf(a.x,b.x); h.y=packbf(a.y,b.y); h.z=packbf(a.z,b.z); h.w=packbf(a.w,b.w);
    l.x=packbf(a.x-bfhi(a.x), b.x-bfhi(b.x));
    l.y=packbf(a.y-bfhi(a.y), b.y-bfhi(b.y));
    l.z=packbf(a.z-bfhi(a.z), b.z-bfhi(b.z));
    l.w=packbf(a.w-bfhi(a.w), b.w-bfhi(b.w));
    *(uint4*)hp = h; *(uint4*)lp = l;
}

#define XR 136                // conv X smem row stride (128 px + pad)
#define WR 36                 // conv W smem row stride
#define XW_WORDS (32*XR)      // 4352
#define WW_WORDS (64*WR)      // 2304

// =====================================================================
// QKV-style bf16-split mma conv: NS weight sets sharing one input. K=64.
// NORM: fuse q/k row sum-of-squares atomics (s=0 -> q slot, s=1 -> k slot)
// PB:   per-batch folded weights at w0 + b*3*4096 + s*4096
// =====================================================================
template<int NS, bool NORM, bool PB>
__global__ __launch_bounds__(256, NS==1?2:1)
void qkvmma_k(const float* __restrict__ in,
              const float* __restrict__ w0,const float* __restrict__ w1,const float* __restrict__ w2,
              float* __restrict__ p0,float* __restrict__ p1,float* __restrict__ p2){
    extern __shared__ uint32_t smu[];
    uint32_t* xh = smu;
    uint32_t* xl = xh + XW_WORDS;
    uint32_t* wsm= xl + XW_WORDS;
    int tid=threadIdx.x, wid=tid>>5, lane=tid&31;
    const float* wptr[3]={w0,w1,w2};
    float* optr[3]={p0,p1,p2};
    size_t bbase=(size_t)blockIdx.y*CC*NN;
    int nblk=blockIdx.x*128;
    const float* ib = in + bbase + nblk;
    {
        int c2=tid>>3, pp=(tid&7)*16;
        const float* r0 = ib + (size_t)(2*c2)*NN;
        const float* r1 = r0 + NN;
        #pragma unroll
        for (int u=0;u<4;u++){
            float4 a=*(const float4*)(r0+pp+u*4);
            float4 b=*(const float4*)(r1+pp+u*4);
            stage_pair4(&xh[c2*XR+pp+u*4], &xl[c2*XR+pp+u*4], a, b);
        }
    }
    #pragma unroll
    for (int s=0;s<NS;s++){
        const float* wp = PB ? (w0 + (size_t)blockIdx.y*3*4096 + s*4096) : wptr[s];
        uint32_t* wh = wsm + s*2*WW_WORDS;
        uint32_t* wl = wh + WW_WORDS;
        #pragma unroll
        for (int i=0;i<4;i++){
            int idx=tid+i*256; int o=idx>>4, c4=idx&15;
            float4 v=*(const float4*)(wp + o*64 + c4*4);
            uint2 h,l;
            h.x=packbf(v.x,v.y); h.y=packbf(v.z,v.w);
            l.x=packbf(v.x-bfhi(v.x), v.y-bfhi(v.y));
            l.y=packbf(v.z-bfhi(v.z), v.w-bfhi(v.w));
            *(uint2*)&wh[o*WR+2*c4]=h;
            *(uint2*)&wl[o*WR+2*c4]=l;
        }
    }
    __syncthreads();
    int wm=wid&3, wn=wid>>2, g=lane>>2, tg=lane&3;
    float acc[NS][8][4];
    #pragma unroll
    for (int s=0;s<NS;s++)
        #pragma unroll
        for (int t=0;t<8;t++)
            #pragma unroll
            for (int e=0;e<4;e++) acc[s][t][e]=0.f;
    #pragma unroll
    for (int ks=0;ks<4;ks++){
        int k2=ks*8;
        uint32_t B0h[8],B1h[8],B0l[8],B1l[8];
        #pragma unroll
        for (int t=0;t<8;t++){
            int n0=wn*64+t*8+g;
            int i0=(k2+tg)*XR+n0, i1=(k2+4+tg)*XR+n0;
            B0h[t]=xh[i0]; B1h[t]=xh[i1];
            B0l[t]=xl[i0]; B1l[t]=xl[i1];
        }
        #pragma unroll
        for (int s=0;s<NS;s++){
            const uint32_t* wh = wsm + s*2*WW_WORDS;
            const uint32_t* wl = wh + WW_WORDS;
            int r0=(wm*16+g)*WR+k2+tg, r1=(wm*16+8+g)*WR+k2+tg;
            uint32_t Ah[4]={wh[r0],wh[r1],wh[r0+4],wh[r1+4]};
            uint32_t Al[4]={wl[r0],wl[r1],wl[r0+4],wl[r1+4]};
            #pragma unroll
            for (int t=0;t<8;t++){
                mma16(acc[s][t],Ah,B0h[t],B1h[t]);
                mma16(acc[s][t],Ah,B0l[t],B1l[t]);
                mma16(acc[s][t],Al,B0h[t],B1h[t]);
            }
        }
    }
    #pragma unroll
    for (int s=0;s<NS;s++){
        float* ob = optr[s] + bbase + nblk;
        #pragma unroll
        for (int t=0;t<8;t++){
            int n0 = wn*64 + t*8 + 2*tg;
            int r0 = wm*16 + g;
            *(float2*)(ob + (size_t)r0*NN + n0)     = make_float2(acc[s][t][0],acc[s][t][1]);
            *(float2*)(ob + (size_t)(r0+8)*NN + n0) = make_float2(acc[s][t][2],acc[s][t][3]);
        }
        if (NORM && s<2){
            float s0=0.f, s1=0.f;
            #pragma unroll
            for (int t=0;t<8;t++){
                s0 += acc[s][t][0]*acc[s][t][0] + acc[s][t][1]*acc[s][t][1];
                s1 += acc[s][t][2]*acc[s][t][2] + acc[s][t][3]*acc[s][t][3];
            }
            s0 += __shfl_xor_sync(0xffffffffu,s0,1); s0 += __shfl_xor_sync(0xffffffffu,s0,2);
            s1 += __shfl_xor_sync(0xffffffffu,s1,1); s1 += __shfl_xor_sync(0xffffffffu,s1,2);
            if (tg==0){
                float* nb = g_norm + (s? BB*CC:0) + blockIdx.y*CC;
                atomicAdd(&nb[wm*16+g],   s0);
                atomicAdd(&nb[wm*16+8+g], s1);
            }
        }
    }
}

// =====================================================================
// K-concat bf16-split mma conv
// =====================================================================
template<int NC,int NB,bool GELU>
__global__ __launch_bounds__(256,2)
void cmma_k(const float* __restrict__ in0,const float* __restrict__ in1,const float* __restrict__ in2,
            const float* __restrict__ w0,const float* __restrict__ w1,const float* __restrict__ w2,
            int wstride,
            const float* __restrict__ bias0,const float* __restrict__ bias1,
            float* __restrict__ outp){
    extern __shared__ uint32_t smu[];
    uint32_t* xh = smu;
    uint32_t* xl = xh + XW_WORDS;
    uint32_t* wh = xl + XW_WORDS;
    uint32_t* wl = wh + WW_WORDS;
    __shared__ float bs[CC];
    int tid=threadIdx.x, wid=tid>>5, lane=tid&31;
    if (NB>0 && tid<CC){ float bv=bias0[tid]; if (NB>1) bv+=bias1[tid]; bs[tid]=bv; }
    const float* ip[3]={in0,in1,in2};
    const float* wp[3]={w0,w1,w2};
    size_t bbase=(size_t)blockIdx.y*CC*NN;
    int nblk=blockIdx.x*128;
    int wm=wid&3, wn=wid>>2, g=lane>>2, tg=lane&3;
    float acc[8][4];
    #pragma unroll
    for (int t=0;t<8;t++){ acc[t][0]=0;acc[t][1]=0;acc[t][2]=0;acc[t][3]=0; }
    #pragma unroll 1
    for (int c=0;c<NC;c++){
        if (c) __syncthreads();
        {
            int c2=tid>>3, pp=(tid&7)*16;
            const float* r0 = ip[c] + bbase + nblk + (size_t)(2*c2)*NN;
            const float* r1 = r0 + NN;
            #pragma unroll
            for (int u=0;u<4;u++){
                float4 a=*(const float4*)(r0+pp+u*4);
                float4 b=*(const float4*)(r1+pp+u*4);
                stage_pair4(&xh[c2*XR+pp+u*4], &xl[c2*XR+pp+u*4], a, b);
            }
        }
        const float* wpc = wp[c];
        #pragma unroll
        for (int i=0;i<4;i++){
            int idx=tid+i*256; int o=idx>>4, c4=idx&15;
            float4 v=*(const float4*)(wpc + (size_t)o*wstride + c4*4);
            uint2 h,l;
            h.x=packbf(v.x,v.y); h.y=packbf(v.z,v.w);
            l.x=packbf(v.x-bfhi(v.x), v.y-bfhi(v.y));
            l.y=packbf(v.z-bfhi(v.z), v.w-bfhi(v.w));
            *(uint2*)&wh[o*WR+2*c4]=h;
            *(uint2*)&wl[o*WR+2*c4]=l;
        }
        __syncthreads();
        #pragma unroll
        for (int ks=0;ks<4;ks++){
            int k2=ks*8;
            int r0=(wm*16+g)*WR+k2+tg, r1=(wm*16+8+g)*WR+k2+tg;
            uint32_t Ah[4]={wh[r0],wh[r1],wh[r0+4],wh[r1+4]};
            uint32_t Al[4]={wl[r0],wl[r1],wl[r0+4],wl[r1+4]};
            #pragma unroll
            for (int t=0;t<8;t++){
                int n0=wn*64+t*8+g;
                int i0=(k2+tg)*XR+n0, i1=(k2+4+tg)*XR+n0;
                uint32_t b0h=xh[i0], b1h=xh[i1], b0l=xl[i0], b1l=xl[i1];
                mma16(acc[t],Ah,b0h,b1h);
                mma16(acc[t],Ah,b0l,b1l);
                mma16(acc[t],Al,b0h,b1h);
            }
        }
    }
    float* ob = outp + bbase + nblk;
    #pragma unroll
    for (int t=0;t<8;t++){
        int n0 = wn*64 + t*8 + 2*tg;
        int r0 = wm*16 + g;
        float2 v0 = make_float2(acc[t][0],acc[t][1]);
        float2 v1 = make_float2(acc[t][2],acc[t][3]);
        if (NB>0){ float b0v=bs[r0], b1v=bs[r0+8];
                   v0.x+=b0v; v0.y+=b0v; v1.x+=b1v; v1.y+=b1v; }
        if (GELU){ v0.x=gelu_f(v0.x); v0.y=gelu_f(v0.y); v1.x=gelu_f(v1.x); v1.y=gelu_f(v1.y); }
        *(float2*)(ob + (size_t)r0*NN + n0)     = v0;
        *(float2*)(ob + (size_t)(r0+8)*NN + n0) = v1;
    }
}

// =====================================================================
// Fused row attention (bf16-split mma)
// =====================================================================
#define SL 192
#define SSP 204
#define SKP 76
#define SVP 72
#define QR 200
#define FA_SMEM ((SL*SSP + 2*32*QR + 64*SKP + SL)*4)   // 228096 B

__global__ __launch_bounds__(256,1)
void fattn_k(const float* __restrict__ Q, const float* __restrict__ K,
             const float* __restrict__ V, const float* __restrict__ res,
             const float* __restrict__ gamma_p, float* __restrict__ out){
    extern __shared__ float sm[];
    float*    sS = sm;
    uint32_t* qh = (uint32_t*)(sS + SL*SSP);
    uint32_t* ql = qh + 32*QR;
    float*    sKV= (float*)(ql + 32*QR);
    float*    sL = sKV + 64*SKP;
    int tid=threadIdx.x, wid=tid>>5, lane=tid&31;
    int b = blockIdx.x / HH, r = blockIdx.x % HH;
    size_t base = (size_t)b*CC*NN + (size_t)r*WW;
    {
        int c2=tid>>3, pp=(tid&7)*24;
        const float* r0 = Q + base + (size_t)(2*c2)*NN;
        const float* r1 = r0 + NN;
        #pragma unroll
        for (int u=0;u<6;u++){
            float4 a=*(const float4*)(r0+pp+u*4);
            float4 b4=*(const float4*)(r1+pp+u*4);
            stage_pair4(&qh[c2*QR+pp+u*4], &ql[c2*QR+pp+u*4], a, b4);
        }
    }
    int wm = wid&1, wn = wid>>1;
    int g = lane>>2, tg = lane&3;
    float acc[12][4];
    for (int jt=0;jt<3;jt++){
        __syncthreads();
        {
            int c = tid>>2, p = tid&3;
            const float4* src = (const float4*)(K + base + (size_t)c*NN + jt*64);
            #pragma unroll
            for (int u=0;u<4;u++)
                *(float4*)(sKV + c*SKP + p*16 + u*4) = src[p*4+u];
        }
        __syncthreads();
        #pragma unroll
        for (int t=0;t<12;t++){acc[t][0]=0;acc[t][1]=0;acc[t][2]=0;acc[t][3]=0;}
        #pragma unroll
        for (int kc=0;kc<4;kc++){
            int k0=kc*16, k2=kc*8;
            uint32_t Ah[2][4], Al[2][4];
            #pragma unroll
            for (int mt=0;mt<2;mt++){
                int m0 = wm*32+mt*16;
                #pragma unroll
                for (int w=0;w<4;w++){
                    int cb  = k0 + 2*tg + (w>>1)*8;
                    int row = m0 + g + (w&1)*8;
                    float v0 = sKV[cb*SKP+row], v1 = sKV[(cb+1)*SKP+row];
                    Ah[mt][w]=packbf(v0,v1);
                    Al[mt][w]=packbf(v0-bfhi(v0), v1-bfhi(v1));
                }
            }
            #pragma unroll
            for (int nt=0;nt<6;nt++){
                int n0 = wn*48+nt*8+g;
                uint32_t b0h=qh[(k2+tg)*QR+n0],   b1h=qh[(k2+4+tg)*QR+n0];
                uint32_t b0l=ql[(k2+tg)*QR+n0],   b1l=ql[(k2+4+tg)*QR+n0];
                #pragma unroll
                for (int mt=0;mt<2;mt++){
                    float* a = acc[mt*6+nt];
                    mma16(a,Ah[mt],b0h,b1h);
                    mma16(a,Ah[mt],b0l,b1l);
                    mma16(a,Al[mt],b0h,b1h);
                }
            }
        }
        #pragma unroll
        for (int mt=0;mt<2;mt++){
            int j0 = jt*64 + wm*32 + mt*16;
            #pragma unroll
            for (int nt=0;nt<6;nt++){
                int n0 = wn*48+nt*8;
                float* a = acc[mt*6+nt];
                *(float2*)&sS[(j0+g)*SSP + n0+2*tg]   = make_float2(a[0],a[1]);
                *(float2*)&sS[(j0+8+g)*SSP + n0+2*tg] = make_float2(a[2],a[3]);
            }
        }
    }
    __syncthreads();
    if (tid < SL){
        int i = tid;
        float m = -3.4e38f;
        #pragma unroll 8
        for (int j=0;j<SL;j++) m = fmaxf(m, sS[j*SSP+i]);
        float s = 0.f;
        #pragma unroll 4
        for (int j2=0;j2<SL/2;j2++){
            float e0 = __expf(sS[(2*j2)*SSP+i]-m);
            float e1 = __expf(sS[(2*j2+1)*SSP+i]-m);
            s += e0+e1;
            sS[(2*j2)*SSP+i]   = __uint_as_float(packbf(e0,e1));
            sS[(2*j2+1)*SSP+i] = __uint_as_float(packbf(e0-bfhi(e0), e1-bfhi(e1)));
        }
        sL[i] = 1.f/s;
    }
    #pragma unroll
    for (int t=0;t<12;t++){acc[t][0]=0;acc[t][1]=0;acc[t][2]=0;acc[t][3]=0;}
    for (int jt=0;jt<3;jt++){
        __syncthreads();
        {
            int c = tid>>2, p = tid&3;
            const float4* src = (const float4*)(V + base + (size_t)c*NN + jt*64);
            #pragma unroll
            for (int u=0;u<4;u++)
                *(float4*)(sKV + c*SVP + p*16 + u*4) = src[p*4+u];
        }
        __syncthreads();
        #pragma unroll
        for (int kc=0;kc<4;kc++){
            uint32_t Ah[2][4], Al[2][4];
            #pragma unroll
            for (int mt=0;mt<2;mt++){
                int m0 = wm*32+mt*16;
                #pragma unroll
                for (int w=0;w<4;w++){
                    int row = m0 + g + (w&1)*8;
                    int jb  = kc*16 + 2*tg + (w>>1)*8;
                    float2 v = *(const float2*)&sKV[row*SVP + jb];
                    Ah[mt][w]=packbf(v.x,v.y);
                    Al[mt][w]=packbf(v.x-bfhi(v.x), v.y-bfhi(v.y));
                }
            }
            int j2g = jt*32 + kc*8;
            #pragma unroll
            for (int nt=0;nt<6;nt++){
                int n0 = wn*48+nt*8+g;
                uint32_t b0h=__float_as_uint(sS[(2*(j2g+tg))*SSP+n0]);
                uint32_t b0l=__float_as_uint(sS[(2*(j2g+tg)+1)*SSP+n0]);
                uint32_t b1h=__float_as_uint(sS[(2*(j2g+4+tg))*SSP+n0]);
                uint32_t b1l=__float_as_uint(sS[(2*(j2g+4+tg)+1)*SSP+n0]);
                #pragma unroll
                for (int mt=0;mt<2;mt++){
                    float* a = acc[mt*6+nt];
                    mma16(a,Ah[mt],b0h,b1h);
                    mma16(a,Ah[mt],b0l,b1l);
                    mma16(a,Al[mt],b0h,b1h);
                }
            }
        }
    }
    float gm = gamma_p[0];
    #pragma unroll
    for (int mt=0;mt<2;mt++){
        int m0 = wm*32+mt*16;
        #pragma unroll
        for (int nt=0;nt<6;nt++){
            int n0 = wn*48+nt*8 + 2*tg;
            float il0 = sL[n0], il1 = sL[n0+1];
            float* a = acc[mt*6+nt];
            float2 r0 = *(const float2*)(res + base + (size_t)(m0+g)*NN + n0);
            float2 r1 = *(const float2*)(res + base + (size_t)(m0+8+g)*NN + n0);
            *(float2*)(out + base + (size_t)(m0+g)*NN + n0) =
                make_float2(gm*a[0]*il0 + r0.x, gm*a[1]*il1 + r0.y);
            *(float2*)(out + base + (size_t)(m0+8+g)*NN + n0) =
                make_float2(gm*a[2]*il0 + r1.x, gm*a[3]*il1 + r1.y);
        }
    }
}

// ---------------- depthwise 3x3 + bias + gelu ----------------
__global__ void dwconv_k(const float* __restrict__ in, const float* __restrict__ w,
                         const float* __restrict__ bias, float* __restrict__ out){
    int idx = blockIdx.x*blockDim.x + threadIdx.x;
    if (idx >= BB*CC*NN) return;
    int n = idx % NN; int bc = idx / NN; int c = bc % CC;
    int y = n / WW, x = n % WW;
    const float* wp = w + c*9;
    const float* ip = in + (size_t)bc*NN;
    float acc = bias[c];
    #pragma unroll
    for (int ky=0;ky<3;ky++){
        int yy = y+ky-1; if (yy<0||yy>=HH) continue;
        #pragma unroll
        for (int kx=0;kx<3;kx++){
            int xx = x+kx-1; if (xx<0||xx>=WW) continue;
            acc += wp[ky*3+kx]*ip[(size_t)yy*WW+xx];
        }
    }
    out[idx] = gelu_f(acc);
}

// ---------------- transpose [b,c,H,W] -> [b,c,W,H] ----------------
__global__ void transpose_k(const float* __restrict__ in, float* __restrict__ out){
    __shared__ float t[32][33];
    const float* ib = in + (size_t)blockIdx.z*NN;
    float* ob = out + (size_t)blockIdx.z*NN;
    int x = blockIdx.x*32 + threadIdx.x;
    #pragma unroll
    for (int k=0;k<32;k+=8)
        t[threadIdx.y+k][threadIdx.x] = ib[(size_t)(blockIdx.y*32+threadIdx.y+k)*WW + x];
    __syncthreads();
    int x2 = blockIdx.y*32 + threadIdx.x;
    #pragma unroll
    for (int k=0;k<32;k+=8)
        ob[(size_t)(blockIdx.x*32+threadIdx.y+k)*HH + x2] = t[threadIdx.x][threadIdx.y+k];
}

// ---------------- zero attn accum + norms ----------------
__global__ void zero_attn_k(){
    int i = blockIdx.x*blockDim.x+threadIdx.x;
    if (i < BB*NHEADS*32*32) g_attn[i]=0.f;
    if (i < 2*BB*CC) g_norm[i]=0.f;
}

// ---------------- channel-attn gram (chunked atomics) ----------------
#define NCHUNK 32
#define CHUNK (NN/NCHUNK)
__global__ void gram_k(const float* __restrict__ q, const float* __restrict__ k){
    int bg = blockIdx.x; int b=bg/NHEADS, g=bg%NHEADS;
    int n0 = blockIdx.y*CHUNK;
    __shared__ float qs[64][33], ks[64][33];
    int c = threadIdx.x>>3, dg = threadIdx.x&7;
    float a0=0,a1=0,a2=0,a3=0;
    const float* qb = q + ((size_t)(b*CC + g*32))*NN + n0;
    const float* kb = k + ((size_t)(b*CC + g*32))*NN + n0;
    for (int tt=0;tt<CHUNK;tt+=64){
        __syncthreads();
        for (int e=threadIdx.x;e<32*64;e+=256){
            int cc=e>>6, t=e&63;
            qs[t][cc]=qb[(size_t)cc*NN + tt + t];
            ks[t][cc]=kb[(size_t)cc*NN + tt + t];
        }
        __syncthreads();
        #pragma unroll 8
        for (int t=0;t<64;t++){
            float qv=qs[t][c];
            a0+=qv*ks[t][dg];    a1+=qv*ks[t][dg+8];
            a2+=qv*ks[t][dg+16]; a3+=qv*ks[t][dg+24];
        }
    }
    float* ab = g_attn + ((size_t)(bg*32+c))*32;
    atomicAdd(&ab[dg],a0);    atomicAdd(&ab[dg+8],a1);
    atomicAdd(&ab[dg+16],a2); atomicAdd(&ab[dg+24],a3);
}

// ---------------- channel-attn softmax ----------------
__global__ void chsm_k(const float* __restrict__ temp){
    int bg = blockIdx.x; int b=bg/NHEADS, g=bg%NHEADS;
    int c = threadIdx.x>>5, d = threadIdx.x&31;
    float nq = fmaxf(sqrtf(g_norm[b*CC + g*32 + c]), 1e-12f);
    float nk = fmaxf(sqrtf(g_norm[BB*CC + b*CC + g*32 + d]), 1e-12f);
    int idx = (bg*32+c)*32+d;
    float v = g_attn[idx]/(nq*nk)*temp[g];
    float m=v;
    #pragma unroll
    for (int o=16;o;o>>=1) m=fmaxf(m,__shfl_xor_sync(0xffffffffu,m,o));
    float e=expf(v-m), s=e;
    #pragma unroll
    for (int o=16;o;o>>=1) s+=__shfl_xor_sync(0xffffffffu,s,o);
    g_attn[idx]=e/s;
}

// ---------------- per-batch folded weights ----------------
// W1[b]  = att_p_w @ blockdiag(attn_b)
// Wrv[b] = row_v_w @ W1[b];  Wcv[b] = col_v_w @ W1[b]
__global__ void wcomb_k(const float* __restrict__ att_p_w,
                        const float* __restrict__ row_v_w,
                        const float* __restrict__ col_v_w){
    int b = blockIdx.x, tid=threadIdx.x;
    __shared__ float sA[NHEADS*32*32];   // attn[b]
    __shared__ float sP[CC*CC];          // att_p_w
    __shared__ float sW1[CC*CC];
    for (int i=tid;i<NHEADS*32*32;i+=256) sA[i]=g_attn[b*NHEADS*32*32+i];
    for (int i=tid;i<CC*CC;i+=256) sP[i]=att_p_w[i];
    __syncthreads();
    for (int i=tid;i<CC*CC;i+=256){
        int o=i>>6, m=i&63; int g=m>>5, d=m&31;
        float s=0.f;
        #pragma unroll
        for (int c=0;c<32;c++) s += sP[o*64+g*32+c]*sA[g*1024+c*32+d];
        sW1[i]=s;
        g_wc[(size_t)b*3*4096 + i]=s;
    }
    __syncthreads();
    for (int i=tid;i<CC*CC;i+=256){
        int o=i>>6, m=i&63;
        float s1=0.f, s2=0.f;
        #pragma unroll
        for (int k=0;k<CC;k++){
            float w1=sW1[k*64+m];
            s1 += row_v_w[o*64+k]*w1;
            s2 += col_v_w[o*64+k]*w1;
        }
        g_wc[(size_t)b*3*4096 + 4096 + i]=s1;
        g_wc[(size_t)b*3*4096 + 8192 + i]=s2;
    }
}

// =======================================================================
extern "C" void kernel_launch(void* const* d_in, const int* in_sizes, int n_in,
                              void* d_out, int out_size){
    const float* x      =(const float*)d_in[0];
    const float* pw_w   =(const float*)d_in[1];
    const float* dw_w   =(const float*)d_in[2];
    const float* dw_b   =(const float*)d_in[3];
    const float* conv2_w=(const float*)d_in[4];
    const float* conv2_b=(const float*)d_in[5];
    const float* conv0_w=(const float*)d_in[6];
    const float* conv0_b=(const float*)d_in[7];
    const float* att_q_w=(const float*)d_in[8];
    const float* att_k_w=(const float*)d_in[9];
    const float* att_v_w=(const float*)d_in[10];
    const float* att_p_w=(const float*)d_in[11];
    const float* temp   =(const float*)d_in[12];
    const float* row_q_w=(const float*)d_in[13];
    const float* row_k_w=(const float*)d_in[14];
    const float* row_v_w=(const float*)d_in[15];
    const float* row_g  =(const float*)d_in[16];
    const float* col_q_w=(const float*)d_in[17];
    const float* col_k_w=(const float*)d_in[18];
    const float* col_v_w=(const float*)d_in[19];
    const float* col_g  =(const float*)d_in[20];
    const float* conv_w =(const float*)d_in[21];
    const float* conv_b =(const float*)d_in[22];
    float* out=(float*)d_out;

    float *t0,*t1,*x1b,*q,*k,*v,*o1,*o2,*o3,*wc;
    cudaGetSymbolAddress((void**)&t0,  g_t0);
    cudaGetSymbolAddress((void**)&t1,  g_t1);
    cudaGetSymbolAddress((void**)&x1b, g_x1);
    cudaGetSymbolAddress((void**)&q,   g_q);
    cudaGetSymbolAddress((void**)&k,   g_k);
    cudaGetSymbolAddress((void**)&v,   g_v);
    cudaGetSymbolAddress((void**)&o1,  g_o1);
    cudaGetSymbolAddress((void**)&o2,  g_o2);
    cudaGetSymbolAddress((void**)&o3,  g_o3);
    cudaGetSymbolAddress((void**)&wc,  g_wc);

    const int SM_Q1 = (2*XW_WORDS + 1*2*WW_WORDS)*4;   // 53248
    const int SM_Q2 = (2*XW_WORDS + 2*2*WW_WORDS)*4;   // 71680
    const int SM_Q3 = (2*XW_WORDS + 3*2*WW_WORDS)*4;   // 90112
    const int SM_CM = (2*XW_WORDS + 2*WW_WORDS)*4;     // 53248
    cudaFuncSetAttribute((const void*)qkvmma_k<1,false,false>, cudaFuncAttributeMaxDynamicSharedMemorySize, SM_Q1);
    cudaFuncSetAttribute((const void*)qkvmma_k<2,false,false>, cudaFuncAttributeMaxDynamicSharedMemorySize, SM_Q2);
    cudaFuncSetAttribute((const void*)qkvmma_k<3,true, false>, cudaFuncAttributeMaxDynamicSharedMemorySize, SM_Q3);
    cudaFuncSetAttribute((const void*)qkvmma_k<3,false,true >, cudaFuncAttributeMaxDynamicSharedMemorySize, SM_Q3);
    cudaFuncSetAttribute((const void*)cmma_k<2,2,false>, cudaFuncAttributeMaxDynamicSharedMemorySize, SM_CM);
    cudaFuncSetAttribute((const void*)cmma_k<3,1,true>,  cudaFuncAttributeMaxDynamicSharedMemorySize, SM_CM);
    cudaFuncSetAttribute((const void*)fattn_k, cudaFuncAttributeMaxDynamicSharedMemorySize, FA_SMEM);

    dim3 mg(NN/128, BB);

    // ---- BSConvU + skip -> x1 ----
    zero_attn_k<<<32,256>>>();
    qkvmma_k<1,false,false><<<mg,256,SM_Q1>>>(x, pw_w,nullptr,nullptr, t0,nullptr,nullptr);
    dwconv_k<<<(BB*CC*NN)/256,256>>>(t0, dw_w, dw_b, t1);
    cmma_k<2,2,false><<<mg,256,SM_CM>>>(t1,x,nullptr, conv2_w,conv0_w,nullptr, 64,
                                        conv2_b,conv0_b, x1b);

    // ---- channel self-attention: qkv conv (+fused norms), gram, softmax ----
    qkvmma_k<3,true,false><<<mg,256,SM_Q3>>>(x1b, att_q_w,att_k_w,att_v_w, q,k,v);
    gram_k<<<dim3(BB*NHEADS,NCHUNK),256>>>(q,k);
    chsm_k<<<BB*NHEADS,1024>>>(temp);

    // ---- fold attn into per-batch weights; one conv of v -> o1, row_v, col_v ----
    wcomb_k<<<BB,256>>>(att_p_w, row_v_w, col_v_w);
    qkvmma_k<3,false,true><<<mg,256,SM_Q3>>>(v, wc,nullptr,nullptr, o1, t0, o3);
    // o1 = channel-attn out; t0 = row V; o3 = col V (normal layout, temp)

    // ---- row attention -> o2 ----
    qkvmma_k<2,false,false><<<mg,256,SM_Q2>>>(x1b, row_q_w,row_k_w,nullptr, q,k,nullptr);
    fattn_k<<<BB*HH,256,FA_SMEM>>>(q,k,t0,x1b,row_g,o2);

    // ---- col attention (transposed) -> o3 ----
    transpose_k<<<dim3(6,6,BB*CC),dim3(32,8)>>>(x1b, t1);          // x1^T
    qkvmma_k<2,false,false><<<mg,256,SM_Q2>>>(t1, col_q_w,col_k_w,nullptr, q,k,nullptr);
    transpose_k<<<dim3(6,6,BB*CC),dim3(32,8)>>>(o3, t0);           // colV^T
    fattn_k<<<BB*WW,256,FA_SMEM>>>(q,k,t0,t1,col_g,v);             // v = o3^T
    transpose_k<<<dim3(6,6,BB*CC),dim3(32,8)>>>(v, o3);

    // ---- fuse ----
    cmma_k<3,1,true><<<mg,256,SM_CM>>>(o1,o2,o3, conv_w,conv_w+64,conv_w+128, 192,
                                       conv_b,nullptr, out);
}

// round 13
// speedup vs baseline: 1.0438x; 1.0438x over previous
#include <cuda_runtime.h>
#include <cuda_bf16.h>
#include <math.h>
#include <stdint.h>

#define BB 4
#define CC 64
#define HH 192
#define WW 192
#define NN (HH*WW)          // 36864
#define PP (BB*NN)
#define NHEADS 2

// ---------------- scratch ----------------
__device__ float g_t0[BB*CC*NN];
__device__ float g_t1[BB*CC*NN];
__device__ float g_x1[BB*CC*NN];
__device__ float g_q [BB*CC*NN];
__device__ float g_k [BB*CC*NN];
__device__ float g_v [BB*CC*NN];
__device__ float g_o1[BB*CC*NN];
__device__ float g_o2[BB*CC*NN];
__device__ float g_o3[BB*CC*NN];
__device__ float g_norm[2*BB*CC];
__device__ float g_attn[BB*NHEADS*32*32];

__device__ __forceinline__ float gelu_f(float v){
    return 0.5f*v*(1.f+erff(v*0.70710678118654752f));
}
// pack two floats as bf16x2: 'lo' -> low 16 bits (even k), 'hi' -> high 16 bits (odd k)
__device__ __forceinline__ uint32_t packbf(float lo, float hi){
    uint32_t r; asm("cvt.rn.bf16x2.f32 %0, %1, %2;" : "=r"(r) : "f"(hi), "f"(lo)); return r;
}
__device__ __forceinline__ float bfhi(float v){
    return __bfloat162float(__float2bfloat16(v));
}
__device__ __forceinline__ void mma16(float* d, const uint32_t* a, uint32_t b0, uint32_t b1){
    asm("mma.sync.aligned.m16n8k16.row.col.f32.bf16.bf16.f32 "
        "{%0,%1,%2,%3},{%4,%5,%6,%7},{%8,%9},{%0,%1,%2,%3};"
        : "+f"(d[0]),"+f"(d[1]),"+f"(d[2]),"+f"(d[3])
        : "r"(a[0]),"r"(a[1]),"r"(a[2]),"r"(a[3]),"r"(b0),"r"(b1));
}
__device__ __forceinline__ void stage_pair4(uint32_t* hp, uint32_t* lp, float4 a, float4 b){
    uint4 h, l;
    h.x=packbf(a.x,b.x); h.y=packbf(a.y,b.y); h.z=packbf(a.z,b.z); h.w=packbf(a.w,b.w);
    l.x=packbf(a.x-bfhi(a.x), b.x-bfhi(b.x));
    l.y=packbf(a.y-bfhi(a.y), b.y-bfhi(b.y));
    l.z=packbf(a.z-bfhi(a.z), b.z-bfhi(b.z));
    l.w=packbf(a.w-bfhi(a.w), b.w-bfhi(b.w));
    *(uint4*)hp = h; *(uint4*)lp = l;
}

#define XR 136                // conv X smem row stride (128 px + pad)
#define WR 36                 // conv W smem row stride
#define XW_WORDS (32*XR)      // 4352
#define WW_WORDS (64*WR)      // 2304

// =====================================================================
// QKV-style bf16-split mma conv: NS weight sets sharing one input. K=64.
// =====================================================================
template<int NS>
__global__ __launch_bounds__(256, NS==1?2:1)
void qkvmma_k(const float* __restrict__ in,
              const float* __restrict__ w0,const float* __restrict__ w1,const float* __restrict__ w2,
              float* __restrict__ p0,float* __restrict__ p1,float* __restrict__ p2){
    extern __shared__ uint32_t smu[];
    uint32_t* xh = smu;
    uint32_t* xl = xh + XW_WORDS;
    uint32_t* wsm= xl + XW_WORDS;
    int tid=threadIdx.x, wid=tid>>5, lane=tid&31;
    const float* wptr[3]={w0,w1,w2};
    float* optr[3]={p0,p1,p2};
    size_t bbase=(size_t)blockIdx.y*CC*NN;
    int nblk=blockIdx.x*128;
    const float* ib = in + bbase + nblk;
    {
        int c2=tid>>3, pp=(tid&7)*16;
        const float* r0 = ib + (size_t)(2*c2)*NN;
        const float* r1 = r0 + NN;
        #pragma unroll
        for (int u=0;u<4;u++){
            float4 a=*(const float4*)(r0+pp+u*4);
            float4 b=*(const float4*)(r1+pp+u*4);
            stage_pair4(&xh[c2*XR+pp+u*4], &xl[c2*XR+pp+u*4], a, b);
        }
    }
    #pragma unroll
    for (int s=0;s<NS;s++){
        const float* wp=wptr[s];
        uint32_t* wh = wsm + s*2*WW_WORDS;
        uint32_t* wl = wh + WW_WORDS;
        #pragma unroll
        for (int i=0;i<4;i++){
            int idx=tid+i*256; int o=idx>>4, c4=idx&15;
            float4 v=*(const float4*)(wp + o*64 + c4*4);
            uint2 h,l;
            h.x=packbf(v.x,v.y); h.y=packbf(v.z,v.w);
            l.x=packbf(v.x-bfhi(v.x), v.y-bfhi(v.y));
            l.y=packbf(v.z-bfhi(v.z), v.w-bfhi(v.w));
            *(uint2*)&wh[o*WR+2*c4]=h;
            *(uint2*)&wl[o*WR+2*c4]=l;
        }
    }
    __syncthreads();
    int wm=wid&3, wn=wid>>2, g=lane>>2, tg=lane&3;
    float acc[NS][8][4];
    #pragma unroll
    for (int s=0;s<NS;s++)
        #pragma unroll
        for (int t=0;t<8;t++)
            #pragma unroll
            for (int e=0;e<4;e++) acc[s][t][e]=0.f;
    #pragma unroll
    for (int ks=0;ks<4;ks++){
        int k2=ks*8;
        uint32_t B0h[8],B1h[8],B0l[8],B1l[8];
        #pragma unroll
        for (int t=0;t<8;t++){
            int n0=wn*64+t*8+g;
            int i0=(k2+tg)*XR+n0, i1=(k2+4+tg)*XR+n0;
            B0h[t]=xh[i0]; B1h[t]=xh[i1];
            B0l[t]=xl[i0]; B1l[t]=xl[i1];
        }
        #pragma unroll
        for (int s=0;s<NS;s++){
            const uint32_t* wh = wsm + s*2*WW_WORDS;
            const uint32_t* wl = wh + WW_WORDS;
            int r0=(wm*16+g)*WR+k2+tg, r1=(wm*16+8+g)*WR+k2+tg;
            uint32_t Ah[4]={wh[r0],wh[r1],wh[r0+4],wh[r1+4]};
            uint32_t Al[4]={wl[r0],wl[r1],wl[r0+4],wl[r1+4]};
            #pragma unroll
            for (int t=0;t<8;t++){
                mma16(acc[s][t],Ah,B0h[t],B1h[t]);
                mma16(acc[s][t],Ah,B0l[t],B1l[t]);
                mma16(acc[s][t],Al,B0h[t],B1h[t]);
            }
        }
    }
    #pragma unroll
    for (int s=0;s<NS;s++){
        float* ob = optr[s] + bbase + nblk;
        #pragma unroll
        for (int t=0;t<8;t++){
            int n0 = wn*64 + t*8 + 2*tg;
            int r0 = wm*16 + g;
            *(float2*)(ob + (size_t)r0*NN + n0)     = make_float2(acc[s][t][0],acc[s][t][1]);
            *(float2*)(ob + (size_t)(r0+8)*NN + n0) = make_float2(acc[s][t][2],acc[s][t][3]);
        }
    }
}

// =====================================================================
// K-concat bf16-split mma conv
// =====================================================================
template<int NC,int NB,bool GELU>
__global__ __launch_bounds__(256,2)
void cmma_k(const float* __restrict__ in0,const float* __restrict__ in1,const float* __restrict__ in2,
            const float* __restrict__ w0,const float* __restrict__ w1,const float* __restrict__ w2,
            int wstride,
            const float* __restrict__ bias0,const float* __restrict__ bias1,
            float* __restrict__ outp){
    extern __shared__ uint32_t smu[];
    uint32_t* xh = smu;
    uint32_t* xl = xh + XW_WORDS;
    uint32_t* wh = xl + XW_WORDS;
    uint32_t* wl = wh + WW_WORDS;
    __shared__ float bs[CC];
    int tid=threadIdx.x, wid=tid>>5, lane=tid&31;
    if (NB>0 && tid<CC){ float bv=bias0[tid]; if (NB>1) bv+=bias1[tid]; bs[tid]=bv; }
    const float* ip[3]={in0,in1,in2};
    const float* wp[3]={w0,w1,w2};
    size_t bbase=(size_t)blockIdx.y*CC*NN;
    int nblk=blockIdx.x*128;
    int wm=wid&3, wn=wid>>2, g=lane>>2, tg=lane&3;
    float acc[8][4];
    #pragma unroll
    for (int t=0;t<8;t++){ acc[t][0]=0;acc[t][1]=0;acc[t][2]=0;acc[t][3]=0; }
    #pragma unroll 1
    for (int c=0;c<NC;c++){
        if (c) __syncthreads();
        {
            int c2=tid>>3, pp=(tid&7)*16;
            const float* r0 = ip[c] + bbase + nblk + (size_t)(2*c2)*NN;
            const float* r1 = r0 + NN;
            #pragma unroll
            for (int u=0;u<4;u++){
                float4 a=*(const float4*)(r0+pp+u*4);
                float4 b=*(const float4*)(r1+pp+u*4);
                stage_pair4(&xh[c2*XR+pp+u*4], &xl[c2*XR+pp+u*4], a, b);
            }
        }
        const float* wpc = wp[c];
        #pragma unroll
        for (int i=0;i<4;i++){
            int idx=tid+i*256; int o=idx>>4, c4=idx&15;
            float4 v=*(const float4*)(wpc + (size_t)o*wstride + c4*4);
            uint2 h,l;
            h.x=packbf(v.x,v.y); h.y=packbf(v.z,v.w);
            l.x=packbf(v.x-bfhi(v.x), v.y-bfhi(v.y));
            l.y=packbf(v.z-bfhi(v.z), v.w-bfhi(v.w));
            *(uint2*)&wh[o*WR+2*c4]=h;
            *(uint2*)&wl[o*WR+2*c4]=l;
        }
        __syncthreads();
        #pragma unroll
        for (int ks=0;ks<4;ks++){
            int k2=ks*8;
            int r0=(wm*16+g)*WR+k2+tg, r1=(wm*16+8+g)*WR+k2+tg;
            uint32_t Ah[4]={wh[r0],wh[r1],wh[r0+4],wh[r1+4]};
            uint32_t Al[4]={wl[r0],wl[r1],wl[r0+4],wl[r1+4]};
            #pragma unroll
            for (int t=0;t<8;t++){
                int n0=wn*64+t*8+g;
                int i0=(k2+tg)*XR+n0, i1=(k2+4+tg)*XR+n0;
                uint32_t b0h=xh[i0], b1h=xh[i1], b0l=xl[i0], b1l=xl[i1];
                mma16(acc[t],Ah,b0h,b1h);
                mma16(acc[t],Ah,b0l,b1l);
                mma16(acc[t],Al,b0h,b1h);
            }
        }
    }
    float* ob = outp + bbase + nblk;
    #pragma unroll
    for (int t=0;t<8;t++){
        int n0 = wn*64 + t*8 + 2*tg;
        int r0 = wm*16 + g;
        float2 v0 = make_float2(acc[t][0],acc[t][1]);
        float2 v1 = make_float2(acc[t][2],acc[t][3]);
        if (NB>0){ float b0v=bs[r0], b1v=bs[r0+8];
                   v0.x+=b0v; v0.y+=b0v; v1.x+=b1v; v1.y+=b1v; }
        if (GELU){ v0.x=gelu_f(v0.x); v0.y=gelu_f(v0.y); v1.x=gelu_f(v1.x); v1.y=gelu_f(v1.y); }
        *(float2*)(ob + (size_t)r0*NN + n0)     = v0;
        *(float2*)(ob + (size_t)(r0+8)*NN + n0) = v1;
    }
}

// =====================================================================
// Fused row attention (bf16-split mma). K and V now PRE-PACKED at staging
// (hi/lo bf16x2 pair-words) so the mma loops are pure LDS + HMMA.
// =====================================================================
#define SL 192
#define SSP 204
#define QR 200   // packed Q stride (192 + 8 pad)
#define KPR 72   // packed K stride: [32 ch-pairs][64 j + 8 pad]
#define VPR 36   // packed V stride: [64 ch][32 j-pairs + 4 pad]
// words: sS 39168 + q 12800 + kv 4608 + sL 192 = 56768 -> 227072 B
#define FA_SMEM ((SL*SSP + 2*32*QR + 2*32*KPR + SL)*4)

__global__ __launch_bounds__(256,1)
void fattn_k(const float* __restrict__ Q, const float* __restrict__ K,
             const float* __restrict__ V, const float* __restrict__ res,
             const float* __restrict__ gamma_p, float* __restrict__ out){
    extern __shared__ float sm[];
    float*    sS = sm;                       // [192][204] fp32 scores -> packed P
    uint32_t* qh = (uint32_t*)(sS + SL*SSP); // [32][200]
    uint32_t* ql = qh + 32*QR;
    uint32_t* kvh= ql + 32*QR;               // K: [32][72] / V: [64][36]
    uint32_t* kvl= kvh + 32*KPR;             // (same byte size both phases)
    float*    sL = (float*)(kvl + 32*KPR);   // [192]
    int tid=threadIdx.x, wid=tid>>5, lane=tid&31;
    int b = blockIdx.x / HH, r = blockIdx.x % HH;
    size_t base = (size_t)b*CC*NN + (size_t)r*WW;
    // stage Q as bf16 hi/lo channel-pair words [k2][i]
    {
        int c2=tid>>3, pp=(tid&7)*24;
        const float* r0 = Q + base + (size_t)(2*c2)*NN;
        const float* r1 = r0 + NN;
        #pragma unroll
        for (int u=0;u<6;u++){
            float4 a=*(const float4*)(r0+pp+u*4);
            float4 b4=*(const float4*)(r1+pp+u*4);
            stage_pair4(&qh[c2*QR+pp+u*4], &ql[c2*QR+pp+u*4], a, b4);
        }
    }
    int wm = wid&1, wn = wid>>1;
    int g = lane>>2, tg = lane&3;
    float acc[12][4];
    // ---- phase 1: S[j][i] = sum_c K[c][j] Q[c][i] ----
    for (int jt=0;jt<3;jt++){
        __syncthreads();
        {   // stage K tile packed: word [c2][j] = pack(K[2c2][j],K[2c2+1][j])
            int c2 = tid>>3, j0 = (tid&7)*8;
            const float* r0 = K + base + (size_t)(2*c2)*NN + jt*64 + j0;
            const float* r1 = r0 + NN;
            float4 a0=*(const float4*)(r0),   a1=*(const float4*)(r0+4);
            float4 b0=*(const float4*)(r1),   b1=*(const float4*)(r1+4);
            stage_pair4(&kvh[c2*KPR+j0],   &kvl[c2*KPR+j0],   a0,b0);
            stage_pair4(&kvh[c2*KPR+j0+4], &kvl[c2*KPR+j0+4], a1,b1);
        }
        __syncthreads();
        #pragma unroll
        for (int t=0;t<12;t++){acc[t][0]=0;acc[t][1]=0;acc[t][2]=0;acc[t][3]=0;}
        #pragma unroll
        for (int kc=0;kc<4;kc++){
            int k2=kc*8;
            uint32_t Ah[2][4], Al[2][4];
            #pragma unroll
            for (int mt=0;mt<2;mt++){
                int m0 = wm*32+mt*16;
                #pragma unroll
                for (int w=0;w<4;w++){
                    int c2p = k2 + tg + (w>>1)*4;
                    int row = m0 + g + (w&1)*8;
                    Ah[mt][w]=kvh[c2p*KPR+row];
                    Al[mt][w]=kvl[c2p*KPR+row];
                }
            }
            #pragma unroll
            for (int nt=0;nt<6;nt++){
                int n0 = wn*48+nt*8+g;
                uint32_t b0h=qh[(k2+tg)*QR+n0],   b1h=qh[(k2+4+tg)*QR+n0];
                uint32_t b0l=ql[(k2+tg)*QR+n0],   b1l=ql[(k2+4+tg)*QR+n0];
                #pragma unroll
                for (int mt=0;mt<2;mt++){
                    float* a = acc[mt*6+nt];
                    mma16(a,Ah[mt],b0h,b1h);
                    mma16(a,Ah[mt],b0l,b1l);
                    mma16(a,Al[mt],b0h,b1h);
                }
            }
        }
        #pragma unroll
        for (int mt=0;mt<2;mt++){
            int j0 = jt*64 + wm*32 + mt*16;
            #pragma unroll
            for (int nt=0;nt<6;nt++){
                int n0 = wn*48+nt*8;
                float* a = acc[mt*6+nt];
                *(float2*)&sS[(j0+g)*SSP + n0+2*tg]   = make_float2(a[0],a[1]);
                *(float2*)&sS[(j0+8+g)*SSP + n0+2*tg] = make_float2(a[2],a[3]);
            }
        }
    }
    __syncthreads();
    // ---- softmax over j per column i, pack P in place (even row=hi, odd=lo) ----
    if (tid < SL){
        int i = tid;
        float m = -3.4e38f;
        #pragma unroll 8
        for (int j=0;j<SL;j++) m = fmaxf(m, sS[j*SSP+i]);
        float s = 0.f;
        #pragma unroll 4
        for (int j2=0;j2<SL/2;j2++){
            float e0 = __expf(sS[(2*j2)*SSP+i]-m);
            float e1 = __expf(sS[(2*j2+1)*SSP+i]-m);
            s += e0+e1;
            sS[(2*j2)*SSP+i]   = __uint_as_float(packbf(e0,e1));
            sS[(2*j2+1)*SSP+i] = __uint_as_float(packbf(e0-bfhi(e0), e1-bfhi(e1)));
        }
        sL[i] = 1.f/s;
    }
    // ---- phase 2: O[c][i] = sum_j V[c][j] P[j][i] ----
    #pragma unroll
    for (int t=0;t<12;t++){acc[t][0]=0;acc[t][1]=0;acc[t][2]=0;acc[t][3]=0;}
    for (int jt=0;jt<3;jt++){
        __syncthreads();
        {   // stage V tile packed: word [c][jp] = pack(V[c][2jp],V[c][2jp+1])
            int c = tid>>2, j20 = (tid&3)*8;
            const float4* src = (const float4*)(V + base + (size_t)c*NN + jt*64 + j20*2);
            #pragma unroll
            for (int u=0;u<4;u++){
                float4 v = src[u];
                uint2 h,l;
                h.x=packbf(v.x,v.y); h.y=packbf(v.z,v.w);
                l.x=packbf(v.x-bfhi(v.x), v.y-bfhi(v.y));
                l.y=packbf(v.z-bfhi(v.z), v.w-bfhi(v.w));
                *(uint2*)&kvh[c*VPR + j20 + 2*u] = h;
                *(uint2*)&kvl[c*VPR + j20 + 2*u] = l;
            }
        }
        __syncthreads();
        #pragma unroll
        for (int kc=0;kc<4;kc++){
            uint32_t Ah[2][4], Al[2][4];
            #pragma unroll
            for (int mt=0;mt<2;mt++){
                int m0 = wm*32+mt*16;
                #pragma unroll
                for (int w=0;w<4;w++){
                    int row = m0 + g + (w&1)*8;
                    int jp  = kc*8 + tg + (w>>1)*4;
                    Ah[mt][w]=kvh[row*VPR+jp];
                    Al[mt][w]=kvl[row*VPR+jp];
                }
            }
            int j2g = jt*32 + kc*8;
            #pragma unroll
            for (int nt=0;nt<6;nt++){
                int n0 = wn*48+nt*8+g;
                uint32_t b0h=__float_as_uint(sS[(2*(j2g+tg))*SSP+n0]);
                uint32_t b0l=__float_as_uint(sS[(2*(j2g+tg)+1)*SSP+n0]);
                uint32_t b1h=__float_as_uint(sS[(2*(j2g+4+tg))*SSP+n0]);
                uint32_t b1l=__float_as_uint(sS[(2*(j2g+4+tg)+1)*SSP+n0]);
                #pragma unroll
                for (int mt=0;mt<2;mt++){
                    float* a = acc[mt*6+nt];
                    mma16(a,Ah[mt],b0h,b1h);
                    mma16(a,Ah[mt],b0l,b1l);
                    mma16(a,Al[mt],b0h,b1h);
                }
            }
        }
    }
    // ---- epilogue ----
    float gm = gamma_p[0];
    #pragma unroll
    for (int mt=0;mt<2;mt++){
        int m0 = wm*32+mt*16;
        #pragma unroll
        for (int nt=0;nt<6;nt++){
            int n0 = wn*48+nt*8 + 2*tg;
            float il0 = sL[n0], il1 = sL[n0+1];
            float* a = acc[mt*6+nt];
            float2 r0 = *(const float2*)(res + base + (size_t)(m0+g)*NN + n0);
            float2 r1 = *(const float2*)(res + base + (size_t)(m0+8+g)*NN + n0);
            *(float2*)(out + base + (size_t)(m0+g)*NN + n0) =
                make_float2(gm*a[0]*il0 + r0.x, gm*a[1]*il1 + r0.y);
            *(float2*)(out + base + (size_t)(m0+8+g)*NN + n0) =
                make_float2(gm*a[2]*il0 + r1.x, gm*a[3]*il1 + r1.y);
        }
    }
}

// ---------------- depthwise 3x3 + bias + gelu ----------------
__global__ void dwconv_k(const float* __restrict__ in, const float* __restrict__ w,
                         const float* __restrict__ bias, float* __restrict__ out){
    int idx = blockIdx.x*blockDim.x + threadIdx.x;
    if (idx >= BB*CC*NN) return;
    int n = idx % NN; int bc = idx / NN; int c = bc % CC;
    int y = n / WW, x = n % WW;
    const float* wp = w + c*9;
    const float* ip = in + (size_t)bc*NN;
    float acc = bias[c];
    #pragma unroll
    for (int ky=0;ky<3;ky++){
        int yy = y+ky-1; if (yy<0||yy>=HH) continue;
        #pragma unroll
        for (int kx=0;kx<3;kx++){
            int xx = x+kx-1; if (xx<0||xx>=WW) continue;
            acc += wp[ky*3+kx]*ip[(size_t)yy*WW+xx];
        }
    }
    out[idx] = gelu_f(acc);
}

// ---------------- transpose [b,c,H,W] -> [b,c,W,H] ----------------
__global__ void transpose_k(const float* __restrict__ in, float* __restrict__ out){
    __shared__ float t[32][33];
    const float* ib = in + (size_t)blockIdx.z*NN;
    float* ob = out + (size_t)blockIdx.z*NN;
    int x = blockIdx.x*32 + threadIdx.x;
    #pragma unroll
    for (int k=0;k<32;k+=8)
        t[threadIdx.y+k][threadIdx.x] = ib[(size_t)(blockIdx.y*32+threadIdx.y+k)*WW + x];
    __syncthreads();
    int x2 = blockIdx.y*32 + threadIdx.x;
    #pragma unroll
    for (int k=0;k<32;k+=8)
        ob[(size_t)(blockIdx.x*32+threadIdx.y+k)*HH + x2] = t[threadIdx.x][threadIdx.y+k];
}

// ---------------- q,k row sum-of-squares ----------------
__global__ void norm_k(const float* __restrict__ q, const float* __restrict__ k){
    int id = blockIdx.x;
    const float* src = (id < BB*CC) ? q : k;
    int bc = id % (BB*CC);
    const float* r = src + (size_t)bc*NN;
    float s=0.f;
    for (int n=threadIdx.x;n<NN;n+=256){ float v=r[n]; s+=v*v; }
    __shared__ float red[256];
    red[threadIdx.x]=s; __syncthreads();
    for (int o=128;o;o>>=1){ if(threadIdx.x<o) red[threadIdx.x]+=red[threadIdx.x+o]; __syncthreads(); }
    if (threadIdx.x==0) g_norm[id]=red[0];
}

__global__ void zero_attn_k(){
    int i = blockIdx.x*blockDim.x+threadIdx.x;
    if (i < BB*NHEADS*32*32) g_attn[i]=0.f;
}

// ---------------- channel-attn gram (chunked atomics) ----------------
#define NCHUNK 32
#define CHUNK (NN/NCHUNK)
__global__ void gram_k(const float* __restrict__ q, const float* __restrict__ k){
    int bg = blockIdx.x; int b=bg/NHEADS, g=bg%NHEADS;
    int n0 = blockIdx.y*CHUNK;
    __shared__ float qs[64][33], ks[64][33];
    int c = threadIdx.x>>3, dg = threadIdx.x&7;
    float a0=0,a1=0,a2=0,a3=0;
    const float* qb = q + ((size_t)(b*CC + g*32))*NN + n0;
    const float* kb = k + ((size_t)(b*CC + g*32))*NN + n0;
    for (int tt=0;tt<CHUNK;tt+=64){
        __syncthreads();
        for (int e=threadIdx.x;e<32*64;e+=256){
            int cc=e>>6, t=e&63;
            qs[t][cc]=qb[(size_t)cc*NN + tt + t];
            ks[t][cc]=kb[(size_t)cc*NN + tt + t];
        }
        __syncthreads();
        #pragma unroll 8
        for (int t=0;t<64;t++){
            float qv=qs[t][c];
            a0+=qv*ks[t][dg];    a1+=qv*ks[t][dg+8];
            a2+=qv*ks[t][dg+16]; a3+=qv*ks[t][dg+24];
        }
    }
    float* ab = g_attn + ((size_t)(bg*32+c))*32;
    atomicAdd(&ab[dg],a0);    atomicAdd(&ab[dg+8],a1);
    atomicAdd(&ab[dg+16],a2); atomicAdd(&ab[dg+24],a3);
}

// ---------------- channel-attn softmax ----------------
__global__ void chsm_k(const float* __restrict__ temp){
    int bg = blockIdx.x; int b=bg/NHEADS, g=bg%NHEADS;
    int c = threadIdx.x>>5, d = threadIdx.x&31;
    float nq = fmaxf(sqrtf(g_norm[b*CC + g*32 + c]), 1e-12f);
    float nk = fmaxf(sqrtf(g_norm[BB*CC + b*CC + g*32 + d]), 1e-12f);
    int idx = (bg*32+c)*32+d;
    float v = g_attn[idx]/(nq*nk)*temp[g];
    float m=v;
    #pragma unroll
    for (int o=16;o;o>>=1) m=fmaxf(m,__shfl_xor_sync(0xffffffffu,m,o));
    float e=expf(v-m), s=e;
    #pragma unroll
    for (int o=16;o;o>>=1) s+=__shfl_xor_sync(0xffffffffu,s,o);
    g_attn[idx]=e/s;
}

// ---------------- mid = attn @ v ----------------
__global__ void attnv_k(const float* __restrict__ v, float* __restrict__ mid){
    __shared__ float4 as4[NHEADS*32*8];
    int b = blockIdx.y;
    int n = blockIdx.x*256 + threadIdx.x;
    const float4* ag = (const float4*)(g_attn + b*NHEADS*32*32);
    for (int i=threadIdx.x;i<NHEADS*32*8;i+=256) as4[i]=ag[i];
    __syncthreads();
    const float* vb = v + (size_t)b*CC*NN + n;
    float* mb = mid + (size_t)b*CC*NN + n;
    #pragma unroll
    for (int g=0;g<NHEADS;g++){
        float vv[32];
        #pragma unroll
        for (int d=0;d<32;d++) vv[d]=vb[(size_t)(g*32+d)*NN];
        #pragma unroll 1
        for (int c=0;c<32;c++){
            float a=0.f;
            #pragma unroll
            for (int d4=0;d4<8;d4++){
                float4 av=as4[(g*32+c)*8+d4];
                a += av.x*vv[d4*4]+av.y*vv[d4*4+1]+av.z*vv[d4*4+2]+av.w*vv[d4*4+3];
            }
            mb[(size_t)(g*32+c)*NN]=a;
        }
    }
}

// =======================================================================
extern "C" void kernel_launch(void* const* d_in, const int* in_sizes, int n_in,
                              void* d_out, int out_size){
    const float* x      =(const float*)d_in[0];
    const float* pw_w   =(const float*)d_in[1];
    const float* dw_w   =(const float*)d_in[2];
    const float* dw_b   =(const float*)d_in[3];
    const float* conv2_w=(const float*)d_in[4];
    const float* conv2_b=(const float*)d_in[5];
    const float* conv0_w=(const float*)d_in[6];
    const float* conv0_b=(const float*)d_in[7];
    const float* att_q_w=(const float*)d_in[8];
    const float* att_k_w=(const float*)d_in[9];
    const float* att_v_w=(const float*)d_in[10];
    const float* att_p_w=(const float*)d_in[11];
    const float* temp   =(const float*)d_in[12];
    const float* row_q_w=(const float*)d_in[13];
    const float* row_k_w=(const float*)d_in[14];
    const float* row_v_w=(const float*)d_in[15];
    const float* row_g  =(const float*)d_in[16];
    const float* col_q_w=(const float*)d_in[17];
    const float* col_k_w=(const float*)d_in[18];
    const float* col_v_w=(const float*)d_in[19];
    const float* col_g  =(const float*)d_in[20];
    const float* conv_w =(const float*)d_in[21];
    const float* conv_b =(const float*)d_in[22];
    float* out=(float*)d_out;

    float *t0,*t1,*x1b,*q,*k,*v,*o1,*o2,*o3;
    cudaGetSymbolAddress((void**)&t0,  g_t0);
    cudaGetSymbolAddress((void**)&t1,  g_t1);
    cudaGetSymbolAddress((void**)&x1b, g_x1);
    cudaGetSymbolAddress((void**)&q,   g_q);
    cudaGetSymbolAddress((void**)&k,   g_k);
    cudaGetSymbolAddress((void**)&v,   g_v);
    cudaGetSymbolAddress((void**)&o1,  g_o1);
    cudaGetSymbolAddress((void**)&o2,  g_o2);
    cudaGetSymbolAddress((void**)&o3,  g_o3);

    const int SM_Q1 = (2*XW_WORDS + 1*2*WW_WORDS)*4;   // 53248
    const int SM_Q2 = (2*XW_WORDS + 2*2*WW_WORDS)*4;   // 71680
    const int SM_Q3 = (2*XW_WORDS + 3*2*WW_WORDS)*4;   // 90112
    const int SM_CM = (2*XW_WORDS + 2*WW_WORDS)*4;     // 53248
    cudaFuncSetAttribute(qkvmma_k<1>, cudaFuncAttributeMaxDynamicSharedMemorySize, SM_Q1);
    cudaFuncSetAttribute(qkvmma_k<2>, cudaFuncAttributeMaxDynamicSharedMemorySize, SM_Q2);
    cudaFuncSetAttribute(qkvmma_k<3>, cudaFuncAttributeMaxDynamicSharedMemorySize, SM_Q3);
    cudaFuncSetAttribute(cmma_k<2,2,false>, cudaFuncAttributeMaxDynamicSharedMemorySize, SM_CM);
    cudaFuncSetAttribute(cmma_k<3,1,true>,  cudaFuncAttributeMaxDynamicSharedMemorySize, SM_CM);
    cudaFuncSetAttribute(fattn_k, cudaFuncAttributeMaxDynamicSharedMemorySize, FA_SMEM);

    dim3 mg(NN/128, BB);
    dim3 cg(NN/256, BB);

    // ---- BSConvU + skip -> x1 ----
    zero_attn_k<<<32,256>>>();
    qkvmma_k<1><<<mg,256,SM_Q1>>>(x, pw_w,nullptr,nullptr, t0,nullptr,nullptr);
    dwconv_k<<<(BB*CC*NN)/256,256>>>(t0, dw_w, dw_b, t1);
    cmma_k<2,2,false><<<mg,256,SM_CM>>>(t1,x,nullptr, conv2_w,conv0_w,nullptr, 64,
                                        conv2_b,conv0_b, x1b);

    // ---- channel self-attention -> o1 ----
    qkvmma_k<3><<<mg,256,SM_Q3>>>(x1b, att_q_w,att_k_w,att_v_w, q,k,v);
    norm_k<<<2*BB*CC,256>>>(q,k);
    gram_k<<<dim3(BB*NHEADS,NCHUNK),256>>>(q,k);
    chsm_k<<<BB*NHEADS,1024>>>(temp);
    attnv_k<<<cg,256>>>(v, t0);
    qkvmma_k<1><<<mg,256,SM_Q1>>>(t0, att_p_w,nullptr,nullptr, o1,nullptr,nullptr);

    // ---- row attention -> o2 ----
    qkvmma_k<2><<<mg,256,SM_Q2>>>(x1b, row_q_w,row_k_w,nullptr, q,k,nullptr);
    qkvmma_k<1><<<mg,256,SM_Q1>>>(o1, row_v_w,nullptr,nullptr, v,nullptr,nullptr);
    fattn_k<<<BB*HH,256,FA_SMEM>>>(q,k,v,x1b,row_g,o2);

    // ---- col attention (transposed) -> o3 ----
    transpose_k<<<dim3(6,6,BB*CC),dim3(32,8)>>>(x1b, t1);
    transpose_k<<<dim3(6,6,BB*CC),dim3(32,8)>>>(o1,  t0);
    qkvmma_k<2><<<mg,256,SM_Q2>>>(t1, col_q_w,col_k_w,nullptr, q,k,nullptr);
    qkvmma_k<1><<<mg,256,SM_Q1>>>(t0, col_v_w,nullptr,nullptr, v,nullptr,nullptr);
    fattn_k<<<BB*WW,256,FA_SMEM>>>(q,k,v,t1,col_g,t0);
    transpose_k<<<dim3(6,6,BB*CC),dim3(32,8)>>>(t0, o3);

    // ---- fuse ----
    cmma_k<3,1,true><<<mg,256,SM_CM>>>(o1,o2,o3, conv_w,conv_w+64,conv_w+128, 192,
                                       conv_b,nullptr, out);
}

// round 14
// speedup vs baseline: 1.0832x; 1.0377x over previous
#include <cuda_runtime.h>
#include <cuda_bf16.h>
#include <math.h>
#include <stdint.h>

#define BB 4
#define CC 64
#define HH 192
#define WW 192
#define NN (HH*WW)          // 36864
#define PP (BB*NN)
#define NHEADS 2

// ---------------- scratch ----------------
__device__ float g_t0[BB*CC*NN];
__device__ float g_t1[BB*CC*NN];
__device__ float g_x1[BB*CC*NN];
__device__ float g_q [BB*CC*NN];
__device__ float g_k [BB*CC*NN];
__device__ float g_v [BB*CC*NN];
__device__ float g_o1[BB*CC*NN];
__device__ float g_o2[BB*CC*NN];
__device__ float g_o3[BB*CC*NN];
__device__ float g_norm[2*BB*CC];
__device__ float g_attn[BB*NHEADS*32*32];
__device__ uint32_t g_mh[2][2048];   // packed M = Wq^T Wk (dir 0=row,1=col)
__device__ uint32_t g_ml[2][2048];

__device__ __forceinline__ float gelu_f(float v){
    return 0.5f*v*(1.f+erff(v*0.70710678118654752f));
}
// pack two floats as bf16x2: 'lo' -> low 16 bits (even k), 'hi' -> high 16 bits (odd k)
__device__ __forceinline__ uint32_t packbf(float lo, float hi){
    uint32_t r; asm("cvt.rn.bf16x2.f32 %0, %1, %2;" : "=r"(r) : "f"(hi), "f"(lo)); return r;
}
__device__ __forceinline__ float bfhi(float v){
    return __bfloat162float(__float2bfloat16(v));
}
__device__ __forceinline__ void mma16(float* d, const uint32_t* a, uint32_t b0, uint32_t b1){
    asm("mma.sync.aligned.m16n8k16.row.col.f32.bf16.bf16.f32 "
        "{%0,%1,%2,%3},{%4,%5,%6,%7},{%8,%9},{%0,%1,%2,%3};"
        : "+f"(d[0]),"+f"(d[1]),"+f"(d[2]),"+f"(d[3])
        : "r"(a[0]),"r"(a[1]),"r"(a[2]),"r"(a[3]),"r"(b0),"r"(b1));
}
__device__ __forceinline__ void stage_pair4(uint32_t* hp, uint32_t* lp, float4 a, float4 b){
    uint4 h, l;
    h.x=packbf(a.x,b.x); h.y=packbf(a.y,b.y); h.z=packbf(a.z,b.z); h.w=packbf(a.w,b.w);
    l.x=packbf(a.x-bfhi(a.x), b.x-bfhi(b.x));
    l.y=packbf(a.y-bfhi(a.y), b.y-bfhi(b.y));
    l.z=packbf(a.z-bfhi(a.z), b.z-bfhi(b.z));
    l.w=packbf(a.w-bfhi(a.w), b.w-bfhi(b.w));
    *(uint4*)hp = h; *(uint4*)lp = l;
}

#define XR 136                // conv X smem row stride (128 px + pad)
#define WR 36                 // conv W smem row stride
#define XW_WORDS (32*XR)      // 4352
#define WW_WORDS (64*WR)      // 2304

// =====================================================================
// QKV-style bf16-split mma conv: NS weight sets sharing one input. K=64.
// =====================================================================
template<int NS>
__global__ __launch_bounds__(256, NS==1?2:1)
void qkvmma_k(const float* __restrict__ in,
              const float* __restrict__ w0,const float* __restrict__ w1,const float* __restrict__ w2,
              float* __restrict__ p0,float* __restrict__ p1,float* __restrict__ p2){
    extern __shared__ uint32_t smu[];
    uint32_t* xh = smu;
    uint32_t* xl = xh + XW_WORDS;
    uint32_t* wsm= xl + XW_WORDS;
    int tid=threadIdx.x, wid=tid>>5, lane=tid&31;
    const float* wptr[3]={w0,w1,w2};
    float* optr[3]={p0,p1,p2};
    size_t bbase=(size_t)blockIdx.y*CC*NN;
    int nblk=blockIdx.x*128;
    const float* ib = in + bbase + nblk;
    {
        int c2=tid>>3, pp=(tid&7)*16;
        const float* r0 = ib + (size_t)(2*c2)*NN;
        const float* r1 = r0 + NN;
        #pragma unroll
        for (int u=0;u<4;u++){
            float4 a=*(const float4*)(r0+pp+u*4);
            float4 b=*(const float4*)(r1+pp+u*4);
            stage_pair4(&xh[c2*XR+pp+u*4], &xl[c2*XR+pp+u*4], a, b);
        }
    }
    #pragma unroll
    for (int s=0;s<NS;s++){
        const float* wp=wptr[s];
        uint32_t* wh = wsm + s*2*WW_WORDS;
        uint32_t* wl = wh + WW_WORDS;
        #pragma unroll
        for (int i=0;i<4;i++){
            int idx=tid+i*256; int o=idx>>4, c4=idx&15;
            float4 v=*(const float4*)(wp + o*64 + c4*4);
            uint2 h,l;
            h.x=packbf(v.x,v.y); h.y=packbf(v.z,v.w);
            l.x=packbf(v.x-bfhi(v.x), v.y-bfhi(v.y));
            l.y=packbf(v.z-bfhi(v.z), v.w-bfhi(v.w));
            *(uint2*)&wh[o*WR+2*c4]=h;
            *(uint2*)&wl[o*WR+2*c4]=l;
        }
    }
    __syncthreads();
    int wm=wid&3, wn=wid>>2, g=lane>>2, tg=lane&3;
    float acc[NS][8][4];
    #pragma unroll
    for (int s=0;s<NS;s++)
        #pragma unroll
        for (int t=0;t<8;t++)
            #pragma unroll
            for (int e=0;e<4;e++) acc[s][t][e]=0.f;
    #pragma unroll
    for (int ks=0;ks<4;ks++){
        int k2=ks*8;
        uint32_t B0h[8],B1h[8],B0l[8],B1l[8];
        #pragma unroll
        for (int t=0;t<8;t++){
            int n0=wn*64+t*8+g;
            int i0=(k2+tg)*XR+n0, i1=(k2+4+tg)*XR+n0;
            B0h[t]=xh[i0]; B1h[t]=xh[i1];
            B0l[t]=xl[i0]; B1l[t]=xl[i1];
        }
        #pragma unroll
        for (int s=0;s<NS;s++){
            const uint32_t* wh = wsm + s*2*WW_WORDS;
            const uint32_t* wl = wh + WW_WORDS;
            int r0=(wm*16+g)*WR+k2+tg, r1=(wm*16+8+g)*WR+k2+tg;
            uint32_t Ah[4]={wh[r0],wh[r1],wh[r0+4],wh[r1+4]};
            uint32_t Al[4]={wl[r0],wl[r1],wl[r0+4],wl[r1+4]};
            #pragma unroll
            for (int t=0;t<8;t++){
                mma16(acc[s][t],Ah,B0h[t],B1h[t]);
                mma16(acc[s][t],Ah,B0l[t],B1l[t]);
                mma16(acc[s][t],Al,B0h[t],B1h[t]);
            }
        }
    }
    #pragma unroll
    for (int s=0;s<NS;s++){
        float* ob = optr[s] + bbase + nblk;
        #pragma unroll
        for (int t=0;t<8;t++){
            int n0 = wn*64 + t*8 + 2*tg;
            int r0 = wm*16 + g;
            *(float2*)(ob + (size_t)r0*NN + n0)     = make_float2(acc[s][t][0],acc[s][t][1]);
            *(float2*)(ob + (size_t)(r0+8)*NN + n0) = make_float2(acc[s][t][2],acc[s][t][3]);
        }
    }
}

// =====================================================================
// K-concat bf16-split mma conv
// =====================================================================
template<int NC,int NB,bool GELU>
__global__ __launch_bounds__(256,2)
void cmma_k(const float* __restrict__ in0,const float* __restrict__ in1,const float* __restrict__ in2,
            const float* __restrict__ w0,const float* __restrict__ w1,const float* __restrict__ w2,
            int wstride,
            const float* __restrict__ bias0,const float* __restrict__ bias1,
            float* __restrict__ outp){
    extern __shared__ uint32_t smu[];
    uint32_t* xh = smu;
    uint32_t* xl = xh + XW_WORDS;
    uint32_t* wh = xl + XW_WORDS;
    uint32_t* wl = wh + WW_WORDS;
    __shared__ float bs[CC];
    int tid=threadIdx.x, wid=tid>>5, lane=tid&31;
    if (NB>0 && tid<CC){ float bv=bias0[tid]; if (NB>1) bv+=bias1[tid]; bs[tid]=bv; }
    const float* ip[3]={in0,in1,in2};
    const float* wp[3]={w0,w1,w2};
    size_t bbase=(size_t)blockIdx.y*CC*NN;
    int nblk=blockIdx.x*128;
    int wm=wid&3, wn=wid>>2, g=lane>>2, tg=lane&3;
    float acc[8][4];
    #pragma unroll
    for (int t=0;t<8;t++){ acc[t][0]=0;acc[t][1]=0;acc[t][2]=0;acc[t][3]=0; }
    #pragma unroll 1
    for (int c=0;c<NC;c++){
        if (c) __syncthreads();
        {
            int c2=tid>>3, pp=(tid&7)*16;
            const float* r0 = ip[c] + bbase + nblk + (size_t)(2*c2)*NN;
            const float* r1 = r0 + NN;
            #pragma unroll
            for (int u=0;u<4;u++){
                float4 a=*(const float4*)(r0+pp+u*4);
                float4 b=*(const float4*)(r1+pp+u*4);
                stage_pair4(&xh[c2*XR+pp+u*4], &xl[c2*XR+pp+u*4], a, b);
            }
        }
        const float* wpc = wp[c];
        #pragma unroll
        for (int i=0;i<4;i++){
            int idx=tid+i*256; int o=idx>>4, c4=idx&15;
            float4 v=*(const float4*)(wpc + (size_t)o*wstride + c4*4);
            uint2 h,l;
            h.x=packbf(v.x,v.y); h.y=packbf(v.z,v.w);
            l.x=packbf(v.x-bfhi(v.x), v.y-bfhi(v.y));
            l.y=packbf(v.z-bfhi(v.z), v.w-bfhi(v.w));
            *(uint2*)&wh[o*WR+2*c4]=h;
            *(uint2*)&wl[o*WR+2*c4]=l;
        }
        __syncthreads();
        #pragma unroll
        for (int ks=0;ks<4;ks++){
            int k2=ks*8;
            int r0=(wm*16+g)*WR+k2+tg, r1=(wm*16+8+g)*WR+k2+tg;
            uint32_t Ah[4]={wh[r0],wh[r1],wh[r0+4],wh[r1+4]};
            uint32_t Al[4]={wl[r0],wl[r1],wl[r0+4],wl[r1+4]};
            #pragma unroll
            for (int t=0;t<8;t++){
                int n0=wn*64+t*8+g;
                int i0=(k2+tg)*XR+n0, i1=(k2+4+tg)*XR+n0;
                uint32_t b0h=xh[i0], b1h=xh[i1], b0l=xl[i0], b1l=xl[i1];
                mma16(acc[t],Ah,b0h,b1h);
                mma16(acc[t],Ah,b0l,b1l);
                mma16(acc[t],Al,b0h,b1h);
            }
        }
    }
    float* ob = outp + bbase + nblk;
    #pragma unroll
    for (int t=0;t<8;t++){
        int n0 = wn*64 + t*8 + 2*tg;
        int r0 = wm*16 + g;
        float2 v0 = make_float2(acc[t][0],acc[t][1]);
        float2 v1 = make_float2(acc[t][2],acc[t][3]);
        if (NB>0){ float b0v=bs[r0], b1v=bs[r0+8];
                   v0.x+=b0v; v0.y+=b0v; v1.x+=b1v; v1.y+=b1v; }
        if (GELU){ v0.x=gelu_f(v0.x); v0.y=gelu_f(v0.y); v1.x=gelu_f(v1.x); v1.y=gelu_f(v1.y); }
        *(float2*)(ob + (size_t)r0*NN + n0)     = v0;
        *(float2*)(ob + (size_t)(r0+8)*NN + n0) = v1;
    }
}

// =====================================================================
// Precompute M = Wq^T @ Wk for row(0)/col(1), packed bf16 hi/lo:
// g_mh[d][bp*64+a] = pack(M[a][2bp], M[a][2bp+1])
// =====================================================================
__global__ void mprep_k(const float* __restrict__ rq, const float* __restrict__ rk,
                        const float* __restrict__ cq, const float* __restrict__ ck){
    int d = blockIdx.x, tid = threadIdx.x;
    const float* Wq = d ? cq : rq;
    const float* Wk = d ? ck : rk;
    __shared__ float sq[CC*CC], sk[CC*CC], smm[CC*CC];
    for (int i=tid;i<CC*CC;i+=256){ sq[i]=Wq[i]; sk[i]=Wk[i]; }
    __syncthreads();
    for (int e=tid;e<CC*CC;e+=256){
        int a=e>>6, b=e&63;
        float s=0.f;
        #pragma unroll
        for (int c=0;c<CC;c++) s += sq[c*64+a]*sk[c*64+b];
        smm[a*64+b]=s;
    }
    __syncthreads();
    for (int e=tid;e<2048;e+=256){
        int bp=e>>6, a=e&63;
        float v0=smm[a*64+2*bp], v1=smm[a*64+2*bp+1];
        g_mh[d][bp*64+a]=packbf(bfhi(v0),bfhi(v1));
        g_ml[d][bp*64+a]=packbf(v0-bfhi(v0), v1-bfhi(v1));
    }
}

// =====================================================================
// Fused row attention with algebraic Q/K elimination:
// S = X^T (Wq^T Wk) X.  Per 64-j tile: Y = M^T-applied (Y[a][j]=sum_b M[a][b]X[b][j])
// computed in-block by mma, packed into K's old slot; then S-tile as before.
// =====================================================================
#define SL 192
#define SSP 204
#define KPR 72   // packed Y stride: [32 apairs][64 j + 8 pad]
#define VPR 36   // packed V stride: [64 ch][32 jpairs + 4 pad]
#define QR 200   // packed X stride (192 + 8 pad)
#define FA_SMEM ((SL*SSP + 2*32*QR + 2*32*KPR + SL)*4)   // 227072 B

__global__ __launch_bounds__(256,1)
void fattn_k(const float* __restrict__ X,
             const uint32_t* __restrict__ mh, const uint32_t* __restrict__ ml,
             const float* __restrict__ V, const float* __restrict__ res,
             const float* __restrict__ gamma_p, float* __restrict__ out){
    extern __shared__ float sm[];
    float*    sS = sm;                       // [192][204] fp32 scores -> packed P
    uint32_t* qh = (uint32_t*)(sS + SL*SSP); // X packed [32 ch-pairs][200]
    uint32_t* ql = qh + 32*QR;
    uint32_t* kvh= ql + 32*QR;               // Y: [32][72] / V: [64][36]
    uint32_t* kvl= kvh + 32*KPR;
    float*    sL = (float*)(kvl + 32*KPR);   // [192]
    int tid=threadIdx.x, wid=tid>>5, lane=tid&31;
    int b = blockIdx.x / HH, r = blockIdx.x % HH;
    size_t base = (size_t)b*CC*NN + (size_t)r*WW;
    // stage X as bf16 hi/lo channel-pair words [c2][i]
    {
        int c2=tid>>3, pp=(tid&7)*24;
        const float* r0 = X + base + (size_t)(2*c2)*NN;
        const float* r1 = r0 + NN;
        #pragma unroll
        for (int u=0;u<6;u++){
            float4 a=*(const float4*)(r0+pp+u*4);
            float4 b4=*(const float4*)(r1+pp+u*4);
            stage_pair4(&qh[c2*QR+pp+u*4], &ql[c2*QR+pp+u*4], a, b4);
        }
    }
    __syncthreads();
    int wm = wid&1, wn = wid>>1;
    int g = lane>>2, tg = lane&3;
    float acc[12][4];
    // ---- phase 1: per jt: Y-tile = M-fold of X; then S[j][i] = sum_a Y[a][j] X[a][i] ----
    for (int jt=0;jt<3;jt++){
        if (jt) __syncthreads();
        {   // compute Y[a][jtile] via mma: D[j][a] = sum_b X[b][j] M[a][b]
            int ymt = wid&3, ywn = wid>>2;
            int jg0 = jt*64 + ymt*16;
            float yac[4][4];
            #pragma unroll
            for (int u=0;u<4;u++){ yac[u][0]=0;yac[u][1]=0;yac[u][2]=0;yac[u][3]=0; }
            #pragma unroll
            for (int kc=0;kc<4;kc++){
                int k2=kc*8;
                uint32_t Ah[4],Al[4];
                Ah[0]=qh[(k2+tg)*QR + jg0+g];   Ah[1]=qh[(k2+tg)*QR + jg0+8+g];
                Ah[2]=qh[(k2+4+tg)*QR + jg0+g]; Ah[3]=qh[(k2+4+tg)*QR + jg0+8+g];
                Al[0]=ql[(k2+tg)*QR + jg0+g];   Al[1]=ql[(k2+tg)*QR + jg0+8+g];
                Al[2]=ql[(k2+4+tg)*QR + jg0+g]; Al[3]=ql[(k2+4+tg)*QR + jg0+8+g];
                #pragma unroll
                for (int u=0;u<4;u++){
                    int n0 = (ywn*4+u)*8;
                    uint32_t b0h = mh[(k2+tg)*64 + n0+g],  b1h = mh[(k2+4+tg)*64 + n0+g];
                    uint32_t b0l = ml[(k2+tg)*64 + n0+g],  b1l = ml[(k2+4+tg)*64 + n0+g];
                    mma16(yac[u],Ah,b0h,b1h);
                    mma16(yac[u],Ah,b0l,b1l);
                    mma16(yac[u],Al,b0h,b1h);
                }
            }
            // pack Y-tile: adjacent a-cols live in-thread -> direct hi/lo pack
            #pragma unroll
            for (int u=0;u<4;u++){
                int ap = (ywn*4+u)*4 + tg;
                int jl = ymt*16 + g;
                float d0=yac[u][0], d1=yac[u][1], d2=yac[u][2], d3=yac[u][3];
                kvh[ap*KPR + jl]   = packbf(bfhi(d0), bfhi(d1));
                kvl[ap*KPR + jl]   = packbf(d0-bfhi(d0), d1-bfhi(d1));
                kvh[ap*KPR + jl+8] = packbf(bfhi(d2), bfhi(d3));
                kvl[ap*KPR + jl+8] = packbf(d2-bfhi(d2), d3-bfhi(d3));
            }
        }
        __syncthreads();
        #pragma unroll
        for (int t=0;t<12;t++){acc[t][0]=0;acc[t][1]=0;acc[t][2]=0;acc[t][3]=0;}
        #pragma unroll
        for (int kc=0;kc<4;kc++){
            int k2=kc*8;
            uint32_t Ah[2][4], Al[2][4];
            #pragma unroll
            for (int mt=0;mt<2;mt++){
                int m0 = wm*32+mt*16;
                #pragma unroll
                for (int w=0;w<4;w++){
                    int c2p = k2 + tg + (w>>1)*4;
                    int row = m0 + g + (w&1)*8;
                    Ah[mt][w]=kvh[c2p*KPR+row];
                    Al[mt][w]=kvl[c2p*KPR+row];
                }
            }
            #pragma unroll
            for (int nt=0;nt<6;nt++){
                int n0 = wn*48+nt*8+g;
                uint32_t b0h=qh[(k2+tg)*QR+n0],   b1h=qh[(k2+4+tg)*QR+n0];
                uint32_t b0l=ql[(k2+tg)*QR+n0],   b1l=ql[(k2+4+tg)*QR+n0];
                #pragma unroll
                for (int mt=0;mt<2;mt++){
                    float* a = acc[mt*6+nt];
                    mma16(a,Ah[mt],b0h,b1h);
                    mma16(a,Ah[mt],b0l,b1l);
                    mma16(a,Al[mt],b0h,b1h);
                }
            }
        }
        #pragma unroll
        for (int mt=0;mt<2;mt++){
            int j0 = jt*64 + wm*32 + mt*16;
            #pragma unroll
            for (int nt=0;nt<6;nt++){
                int n0 = wn*48+nt*8;
                float* a = acc[mt*6+nt];
                *(float2*)&sS[(j0+g)*SSP + n0+2*tg]   = make_float2(a[0],a[1]);
                *(float2*)&sS[(j0+8+g)*SSP + n0+2*tg] = make_float2(a[2],a[3]);
            }
        }
    }
    __syncthreads();
    // ---- softmax over j per column i, pack P in place (even row=hi, odd=lo) ----
    if (tid < SL){
        int i = tid;
        float m = -3.4e38f;
        #pragma unroll 8
        for (int j=0;j<SL;j++) m = fmaxf(m, sS[j*SSP+i]);
        float s = 0.f;
        #pragma unroll 4
        for (int j2=0;j2<SL/2;j2++){
            float e0 = __expf(sS[(2*j2)*SSP+i]-m);
            float e1 = __expf(sS[(2*j2+1)*SSP+i]-m);
            s += e0+e1;
            sS[(2*j2)*SSP+i]   = __uint_as_float(packbf(e0,e1));
            sS[(2*j2+1)*SSP+i] = __uint_as_float(packbf(e0-bfhi(e0), e1-bfhi(e1)));
        }
        sL[i] = 1.f/s;
    }
    // ---- phase 2: O[c][i] = sum_j V[c][j] P[j][i] ----
    #pragma unroll
    for (int t=0;t<12;t++){acc[t][0]=0;acc[t][1]=0;acc[t][2]=0;acc[t][3]=0;}
    for (int jt=0;jt<3;jt++){
        __syncthreads();
        {   // stage V tile packed: word [c][jp] = pack(V[c][2jp],V[c][2jp+1])
            int c = tid>>2, j20 = (tid&3)*8;
            const float4* src = (const float4*)(V + base + (size_t)c*NN + jt*64 + j20*2);
            #pragma unroll
            for (int u=0;u<4;u++){
                float4 v = src[u];
                uint2 h,l;
                h.x=packbf(v.x,v.y); h.y=packbf(v.z,v.w);
                l.x=packbf(v.x-bfhi(v.x), v.y-bfhi(v.y));
                l.y=packbf(v.z-bfhi(v.z), v.w-bfhi(v.w));
                *(uint2*)&kvh[c*VPR + j20 + 2*u] = h;
                *(uint2*)&kvl[c*VPR + j20 + 2*u] = l;
            }
        }
        __syncthreads();
        #pragma unroll
        for (int kc=0;kc<4;kc++){
            uint32_t Ah[2][4], Al[2][4];
            #pragma unroll
            for (int mt=0;mt<2;mt++){
                int m0 = wm*32+mt*16;
                #pragma unroll
                for (int w=0;w<4;w++){
                    int row = m0 + g + (w&1)*8;
                    int jp  = kc*8 + tg + (w>>1)*4;
                    Ah[mt][w]=kvh[row*VPR+jp];
                    Al[mt][w]=kvl[row*VPR+jp];
                }
            }
            int j2g = jt*32 + kc*8;
            #pragma unroll
            for (int nt=0;nt<6;nt++){
                int n0 = wn*48+nt*8+g;
                uint32_t b0h=__float_as_uint(sS[(2*(j2g+tg))*SSP+n0]);
                uint32_t b0l=__float_as_uint(sS[(2*(j2g+tg)+1)*SSP+n0]);
                uint32_t b1h=__float_as_uint(sS[(2*(j2g+4+tg))*SSP+n0]);
                uint32_t b1l=__float_as_uint(sS[(2*(j2g+4+tg)+1)*SSP+n0]);
                #pragma unroll
                for (int mt=0;mt<2;mt++){
                    float* a = acc[mt*6+nt];
                    mma16(a,Ah[mt],b0h,b1h);
                    mma16(a,Ah[mt],b0l,b1l);
                    mma16(a,Al[mt],b0h,b1h);
                }
            }
        }
    }
    // ---- epilogue ----
    float gm = gamma_p[0];
    #pragma unroll
    for (int mt=0;mt<2;mt++){
        int m0 = wm*32+mt*16;
        #pragma unroll
        for (int nt=0;nt<6;nt++){
            int n0 = wn*48+nt*8 + 2*tg;
            float il0 = sL[n0], il1 = sL[n0+1];
            float* a = acc[mt*6+nt];
            float2 r0 = *(const float2*)(res + base + (size_t)(m0+g)*NN + n0);
            float2 r1 = *(const float2*)(res + base + (size_t)(m0+8+g)*NN + n0);
            *(float2*)(out + base + (size_t)(m0+g)*NN + n0) =
                make_float2(gm*a[0]*il0 + r0.x, gm*a[1]*il1 + r0.y);
            *(float2*)(out + base + (size_t)(m0+8+g)*NN + n0) =
                make_float2(gm*a[2]*il0 + r1.x, gm*a[3]*il1 + r1.y);
        }
    }
}

// ---------------- depthwise 3x3 + bias + gelu ----------------
__global__ void dwconv_k(const float* __restrict__ in, const float* __restrict__ w,
                         const float* __restrict__ bias, float* __restrict__ out){
    int idx = blockIdx.x*blockDim.x + threadIdx.x;
    if (idx >= BB*CC*NN) return;
    int n = idx % NN; int bc = idx / NN; int c = bc % CC;
    int y = n / WW, x = n % WW;
    const float* wp = w + c*9;
    const float* ip = in + (size_t)bc*NN;
    float acc = bias[c];
    #pragma unroll
    for (int ky=0;ky<3;ky++){
        int yy = y+ky-1; if (yy<0||yy>=HH) continue;
        #pragma unroll
        for (int kx=0;kx<3;kx++){
            int xx = x+kx-1; if (xx<0||xx>=WW) continue;
            acc += wp[ky*3+kx]*ip[(size_t)yy*WW+xx];
        }
    }
    out[idx] = gelu_f(acc);
}

// ---------------- transpose [b,c,H,W] -> [b,c,W,H] ----------------
__global__ void transpose_k(const float* __restrict__ in, float* __restrict__ out){
    __shared__ float t[32][33];
    const float* ib = in + (size_t)blockIdx.z*NN;
    float* ob = out + (size_t)blockIdx.z*NN;
    int x = blockIdx.x*32 + threadIdx.x;
    #pragma unroll
    for (int k=0;k<32;k+=8)
        t[threadIdx.y+k][threadIdx.x] = ib[(size_t)(blockIdx.y*32+threadIdx.y+k)*WW + x];
    __syncthreads();
    int x2 = blockIdx.y*32 + threadIdx.x;
    #pragma unroll
    for (int k=0;k<32;k+=8)
        ob[(size_t)(blockIdx.x*32+threadIdx.y+k)*HH + x2] = t[threadIdx.x][threadIdx.y+k];
}

// ---------------- q,k row sum-of-squares ----------------
__global__ void norm_k(const float* __restrict__ q, const float* __restrict__ k){
    int id = blockIdx.x;
    const float* src = (id < BB*CC) ? q : k;
    int bc = id % (BB*CC);
    const float* r = src + (size_t)bc*NN;
    float s=0.f;
    for (int n=threadIdx.x;n<NN;n+=256){ float v=r[n]; s+=v*v; }
    __shared__ float red[256];
    red[threadIdx.x]=s; __syncthreads();
    for (int o=128;o;o>>=1){ if(threadIdx.x<o) red[threadIdx.x]+=red[threadIdx.x+o]; __syncthreads(); }
    if (threadIdx.x==0) g_norm[id]=red[0];
}

__global__ void zero_attn_k(){
    int i = blockIdx.x*blockDim.x+threadIdx.x;
    if (i < BB*NHEADS*32*32) g_attn[i]=0.f;
}

// ---------------- channel-attn gram (chunked atomics) ----------------
#define NCHUNK 32
#define CHUNK (NN/NCHUNK)
__global__ void gram_k(const float* __restrict__ q, const float* __restrict__ k){
    int bg = blockIdx.x; int b=bg/NHEADS, g=bg%NHEADS;
    int n0 = blockIdx.y*CHUNK;
    __shared__ float qs[64][33], ks[64][33];
    int c = threadIdx.x>>3, dg = threadIdx.x&7;
    float a0=0,a1=0,a2=0,a3=0;
    const float* qb = q + ((size_t)(b*CC + g*32))*NN + n0;
    const float* kb = k + ((size_t)(b*CC + g*32))*NN + n0;
    for (int tt=0;tt<CHUNK;tt+=64){
        __syncthreads();
        for (int e=threadIdx.x;e<32*64;e+=256){
            int cc=e>>6, t=e&63;
            qs[t][cc]=qb[(size_t)cc*NN + tt + t];
            ks[t][cc]=kb[(size_t)cc*NN + tt + t];
        }
        __syncthreads();
        #pragma unroll 8
        for (int t=0;t<64;t++){
            float qv=qs[t][c];
            a0+=qv*ks[t][dg];    a1+=qv*ks[t][dg+8];
            a2+=qv*ks[t][dg+16]; a3+=qv*ks[t][dg+24];
        }
    }
    float* ab = g_attn + ((size_t)(bg*32+c))*32;
    atomicAdd(&ab[dg],a0);    atomicAdd(&ab[dg+8],a1);
    atomicAdd(&ab[dg+16],a2); atomicAdd(&ab[dg+24],a3);
}

// ---------------- channel-attn softmax ----------------
__global__ void chsm_k(const float* __restrict__ temp){
    int bg = blockIdx.x; int b=bg/NHEADS, g=bg%NHEADS;
    int c = threadIdx.x>>5, d = threadIdx.x&31;
    float nq = fmaxf(sqrtf(g_norm[b*CC + g*32 + c]), 1e-12f);
    float nk = fmaxf(sqrtf(g_norm[BB*CC + b*CC + g*32 + d]), 1e-12f);
    int idx = (bg*32+c)*32+d;
    float v = g_attn[idx]/(nq*nk)*temp[g];
    float m=v;
    #pragma unroll
    for (int o=16;o;o>>=1) m=fmaxf(m,__shfl_xor_sync(0xffffffffu,m,o));
    float e=expf(v-m), s=e;
    #pragma unroll
    for (int o=16;o;o>>=1) s+=__shfl_xor_sync(0xffffffffu,s,o);
    g_attn[idx]=e/s;
}

// ---------------- mid = attn @ v ----------------
__global__ void attnv_k(const float* __restrict__ v, float* __restrict__ mid){
    __shared__ float4 as4[NHEADS*32*8];
    int b = blockIdx.y;
    int n = blockIdx.x*256 + threadIdx.x;
    const float4* ag = (const float4*)(g_attn + b*NHEADS*32*32);
    for (int i=threadIdx.x;i<NHEADS*32*8;i+=256) as4[i]=ag[i];
    __syncthreads();
    const float* vb = v + (size_t)b*CC*NN + n;
    float* mb = mid + (size_t)b*CC*NN + n;
    #pragma unroll
    for (int g=0;g<NHEADS;g++){
        float vv[32];
        #pragma unroll
        for (int d=0;d<32;d++) vv[d]=vb[(size_t)(g*32+d)*NN];
        #pragma unroll 1
        for (int c=0;c<32;c++){
            float a=0.f;
            #pragma unroll
            for (int d4=0;d4<8;d4++){
                float4 av=as4[(g*32+c)*8+d4];
                a += av.x*vv[d4*4]+av.y*vv[d4*4+1]+av.z*vv[d4*4+2]+av.w*vv[d4*4+3];
            }
            mb[(size_t)(g*32+c)*NN]=a;
        }
    }
}

// =======================================================================
extern "C" void kernel_launch(void* const* d_in, const int* in_sizes, int n_in,
                              void* d_out, int out_size){
    const float* x      =(const float*)d_in[0];
    const float* pw_w   =(const float*)d_in[1];
    const float* dw_w   =(const float*)d_in[2];
    const float* dw_b   =(const float*)d_in[3];
    const float* conv2_w=(const float*)d_in[4];
    const float* conv2_b=(const float*)d_in[5];
    const float* conv0_w=(const float*)d_in[6];
    const float* conv0_b=(const float*)d_in[7];
    const float* att_q_w=(const float*)d_in[8];
    const float* att_k_w=(const float*)d_in[9];
    const float* att_v_w=(const float*)d_in[10];
    const float* att_p_w=(const float*)d_in[11];
    const float* temp   =(const float*)d_in[12];
    const float* row_q_w=(const float*)d_in[13];
    const float* row_k_w=(const float*)d_in[14];
    const float* row_v_w=(const float*)d_in[15];
    const float* row_g  =(const float*)d_in[16];
    const float* col_q_w=(const float*)d_in[17];
    const float* col_k_w=(const float*)d_in[18];
    const float* col_v_w=(const float*)d_in[19];
    const float* col_g  =(const float*)d_in[20];
    const float* conv_w =(const float*)d_in[21];
    const float* conv_b =(const float*)d_in[22];
    float* out=(float*)d_out;

    float *t0,*t1,*x1b,*q,*k,*v,*o1,*o2,*o3;
    uint32_t *mh,*ml;
    cudaGetSymbolAddress((void**)&t0,  g_t0);
    cudaGetSymbolAddress((void**)&t1,  g_t1);
    cudaGetSymbolAddress((void**)&x1b, g_x1);
    cudaGetSymbolAddress((void**)&q,   g_q);
    cudaGetSymbolAddress((void**)&k,   g_k);
    cudaGetSymbolAddress((void**)&v,   g_v);
    cudaGetSymbolAddress((void**)&o1,  g_o1);
    cudaGetSymbolAddress((void**)&o2,  g_o2);
    cudaGetSymbolAddress((void**)&o3,  g_o3);
    cudaGetSymbolAddress((void**)&mh,  g_mh);
    cudaGetSymbolAddress((void**)&ml,  g_ml);

    const int SM_Q1 = (2*XW_WORDS + 1*2*WW_WORDS)*4;   // 53248
    const int SM_Q3 = (2*XW_WORDS + 3*2*WW_WORDS)*4;   // 90112
    const int SM_CM = (2*XW_WORDS + 2*WW_WORDS)*4;     // 53248
    cudaFuncSetAttribute(qkvmma_k<1>, cudaFuncAttributeMaxDynamicSharedMemorySize, SM_Q1);
    cudaFuncSetAttribute(qkvmma_k<3>, cudaFuncAttributeMaxDynamicSharedMemorySize, SM_Q3);
    cudaFuncSetAttribute(cmma_k<2,2,false>, cudaFuncAttributeMaxDynamicSharedMemorySize, SM_CM);
    cudaFuncSetAttribute(cmma_k<3,1,true>,  cudaFuncAttributeMaxDynamicSharedMemorySize, SM_CM);
    cudaFuncSetAttribute(fattn_k, cudaFuncAttributeMaxDynamicSharedMemorySize, FA_SMEM);

    dim3 mg(NN/128, BB);
    dim3 cg(NN/256, BB);

    // ---- prologue: zero accums + precompute bilinear M matrices ----
    zero_attn_k<<<32,256>>>();
    mprep_k<<<2,256>>>(row_q_w,row_k_w,col_q_w,col_k_w);

    // ---- BSConvU + skip -> x1 ----
    qkvmma_k<1><<<mg,256,SM_Q1>>>(x, pw_w,nullptr,nullptr, t0,nullptr,nullptr);
    dwconv_k<<<(BB*CC*NN)/256,256>>>(t0, dw_w, dw_b, t1);
    cmma_k<2,2,false><<<mg,256,SM_CM>>>(t1,x,nullptr, conv2_w,conv0_w,nullptr, 64,
                                        conv2_b,conv0_b, x1b);

    // ---- channel self-attention -> o1 ----
    qkvmma_k<3><<<mg,256,SM_Q3>>>(x1b, att_q_w,att_k_w,att_v_w, q,k,v);
    norm_k<<<2*BB*CC,256>>>(q,k);
    gram_k<<<dim3(BB*NHEADS,NCHUNK),256>>>(q,k);
    chsm_k<<<BB*NHEADS,1024>>>(temp);
    attnv_k<<<cg,256>>>(v, t0);
    qkvmma_k<1><<<mg,256,SM_Q1>>>(t0, att_p_w,nullptr,nullptr, o1,nullptr,nullptr);

    // ---- row attention -> o2 (Q/K folded into fattn via M) ----
    qkvmma_k<1><<<mg,256,SM_Q1>>>(o1, row_v_w,nullptr,nullptr, v,nullptr,nullptr);
    fattn_k<<<BB*HH,256,FA_SMEM>>>(x1b, mh, ml, v, x1b, row_g, o2);

    // ---- col attention (transposed) -> o3 ----
    transpose_k<<<dim3(6,6,BB*CC),dim3(32,8)>>>(x1b, t1);
    transpose_k<<<dim3(6,6,BB*CC),dim3(32,8)>>>(o1,  t0);
    qkvmma_k<1><<<mg,256,SM_Q1>>>(t0, col_v_w,nullptr,nullptr, v,nullptr,nullptr);
    fattn_k<<<BB*WW,256,FA_SMEM>>>(t1, mh+2048, ml+2048, v, t1, col_g, q);
    transpose_k<<<dim3(6,6,BB*CC),dim3(32,8)>>>(q, o3);

    // ---- fuse ----
    cmma_k<3,1,true><<<mg,256,SM_CM>>>(o1,o2,o3, conv_w,conv_w+64,conv_w+128, 192,
                                       conv_b,nullptr, out);
}

// round 15
// speedup vs baseline: 1.1152x; 1.0296x over previous
#include <cuda_runtime.h>
#include <cuda_bf16.h>
#include <math.h>
#include <stdint.h>

#define BB 4
#define CC 64
#define HH 192
#define WW 192
#define NN (HH*WW)          // 36864
#define PP (BB*NN)
#define NHEADS 2

// ---------------- scratch ----------------
__device__ float g_t0[BB*CC*NN];
__device__ float g_t1[BB*CC*NN];
__device__ float g_x1[BB*CC*NN];
__device__ float g_q [BB*CC*NN];
__device__ float g_k [BB*CC*NN];
__device__ float g_v [BB*CC*NN];
__device__ float g_o1[BB*CC*NN];
__device__ float g_o2[BB*CC*NN];
__device__ float g_o3[BB*CC*NN];
__device__ float g_norm[2*BB*CC];
__device__ float g_attn[BB*NHEADS*32*32];
__device__ float g_w1[BB*CC*CC];     // per-batch folded weight W1 = att_p_w @ BD(attn)
__device__ uint32_t g_mh[2][2048];   // packed M = Wq^T Wk (dir 0=row,1=col)
__device__ uint32_t g_ml[2][2048];

__device__ __forceinline__ float gelu_f(float v){
    return 0.5f*v*(1.f+erff(v*0.70710678118654752f));
}
__device__ __forceinline__ uint32_t packbf(float lo, float hi){
    uint32_t r; asm("cvt.rn.bf16x2.f32 %0, %1, %2;" : "=r"(r) : "f"(hi), "f"(lo)); return r;
}
__device__ __forceinline__ float bfhi(float v){
    return __bfloat162float(__float2bfloat16(v));
}
__device__ __forceinline__ void mma16(float* d, const uint32_t* a, uint32_t b0, uint32_t b1){
    asm("mma.sync.aligned.m16n8k16.row.col.f32.bf16.bf16.f32 "
        "{%0,%1,%2,%3},{%4,%5,%6,%7},{%8,%9},{%0,%1,%2,%3};"
        : "+f"(d[0]),"+f"(d[1]),"+f"(d[2]),"+f"(d[3])
        : "r"(a[0]),"r"(a[1]),"r"(a[2]),"r"(a[3]),"r"(b0),"r"(b1));
}
__device__ __forceinline__ void stage_pair4(uint32_t* hp, uint32_t* lp, float4 a, float4 b){
    uint4 h, l;
    h.x=packbf(a.x,b.x); h.y=packbf(a.y,b.y); h.z=packbf(a.z,b.z); h.w=packbf(a.w,b.w);
    l.x=packbf(a.x-bfhi(a.x), b.x-bfhi(b.x));
    l.y=packbf(a.y-bfhi(a.y), b.y-bfhi(b.y));
    l.z=packbf(a.z-bfhi(a.z), b.z-bfhi(b.z));
    l.w=packbf(a.w-bfhi(a.w), b.w-bfhi(b.w));
    *(uint4*)hp = h; *(uint4*)lp = l;
}

#define XR 136                // conv X smem row stride (128 px + pad)
#define WR 36                 // conv W smem row stride
#define XW_WORDS (32*XR)      // 4352
#define WW_WORDS (64*WR)      // 2304

// =====================================================================
// QKV-style bf16-split mma conv: NS weight sets sharing one input. K=64.
// =====================================================================
template<int NS>
__global__ __launch_bounds__(256, NS==1?2:1)
void qkvmma_k(const float* __restrict__ in,
              const float* __restrict__ w0,const float* __restrict__ w1,const float* __restrict__ w2,
              float* __restrict__ p0,float* __restrict__ p1,float* __restrict__ p2){
    extern __shared__ uint32_t smu[];
    uint32_t* xh = smu;
    uint32_t* xl = xh + XW_WORDS;
    uint32_t* wsm= xl + XW_WORDS;
    int tid=threadIdx.x, wid=tid>>5, lane=tid&31;
    const float* wptr[3]={w0,w1,w2};
    float* optr[3]={p0,p1,p2};
    size_t bbase=(size_t)blockIdx.y*CC*NN;
    int nblk=blockIdx.x*128;
    const float* ib = in + bbase + nblk;
    {
        int c2=tid>>3, pp=(tid&7)*16;
        const float* r0 = ib + (size_t)(2*c2)*NN;
        const float* r1 = r0 + NN;
        #pragma unroll
        for (int u=0;u<4;u++){
            float4 a=*(const float4*)(r0+pp+u*4);
            float4 b=*(const float4*)(r1+pp+u*4);
            stage_pair4(&xh[c2*XR+pp+u*4], &xl[c2*XR+pp+u*4], a, b);
        }
    }
    #pragma unroll
    for (int s=0;s<NS;s++){
        const float* wp=wptr[s];
        uint32_t* wh = wsm + s*2*WW_WORDS;
        uint32_t* wl = wh + WW_WORDS;
        #pragma unroll
        for (int i=0;i<4;i++){
            int idx=tid+i*256; int o=idx>>4, c4=idx&15;
            float4 v=*(const float4*)(wp + o*64 + c4*4);
            uint2 h,l;
            h.x=packbf(v.x,v.y); h.y=packbf(v.z,v.w);
            l.x=packbf(v.x-bfhi(v.x), v.y-bfhi(v.y));
            l.y=packbf(v.z-bfhi(v.z), v.w-bfhi(v.w));
            *(uint2*)&wh[o*WR+2*c4]=h;
            *(uint2*)&wl[o*WR+2*c4]=l;
        }
    }
    __syncthreads();
    int wm=wid&3, wn=wid>>2, g=lane>>2, tg=lane&3;
    float acc[NS][8][4];
    #pragma unroll
    for (int s=0;s<NS;s++)
        #pragma unroll
        for (int t=0;t<8;t++)
            #pragma unroll
            for (int e=0;e<4;e++) acc[s][t][e]=0.f;
    #pragma unroll
    for (int ks=0;ks<4;ks++){
        int k2=ks*8;
        uint32_t B0h[8],B1h[8],B0l[8],B1l[8];
        #pragma unroll
        for (int t=0;t<8;t++){
            int n0=wn*64+t*8+g;
            int i0=(k2+tg)*XR+n0, i1=(k2+4+tg)*XR+n0;
            B0h[t]=xh[i0]; B1h[t]=xh[i1];
            B0l[t]=xl[i0]; B1l[t]=xl[i1];
        }
        #pragma unroll
        for (int s=0;s<NS;s++){
            const uint32_t* wh = wsm + s*2*WW_WORDS;
            const uint32_t* wl = wh + WW_WORDS;
            int r0=(wm*16+g)*WR+k2+tg, r1=(wm*16+8+g)*WR+k2+tg;
            uint32_t Ah[4]={wh[r0],wh[r1],wh[r0+4],wh[r1+4]};
            uint32_t Al[4]={wl[r0],wl[r1],wl[r0+4],wl[r1+4]};
            #pragma unroll
            for (int t=0;t<8;t++){
                mma16(acc[s][t],Ah,B0h[t],B1h[t]);
                mma16(acc[s][t],Ah,B0l[t],B1l[t]);
                mma16(acc[s][t],Al,B0h[t],B1h[t]);
            }
        }
    }
    #pragma unroll
    for (int s=0;s<NS;s++){
        float* ob = optr[s] + bbase + nblk;
        #pragma unroll
        for (int t=0;t<8;t++){
            int n0 = wn*64 + t*8 + 2*tg;
            int r0 = wm*16 + g;
            *(float2*)(ob + (size_t)r0*NN + n0)     = make_float2(acc[s][t][0],acc[s][t][1]);
            *(float2*)(ob + (size_t)(r0+8)*NN + n0) = make_float2(acc[s][t][2],acc[s][t][3]);
        }
    }
}

// =====================================================================
// K-concat bf16-split mma conv
// =====================================================================
template<int NC,int NB,bool GELU>
__global__ __launch_bounds__(256,2)
void cmma_k(const float* __restrict__ in0,const float* __restrict__ in1,const float* __restrict__ in2,
            const float* __restrict__ w0,const float* __restrict__ w1,const float* __restrict__ w2,
            int wstride,
            const float* __restrict__ bias0,const float* __restrict__ bias1,
            float* __restrict__ outp){
    extern __shared__ uint32_t smu[];
    uint32_t* xh = smu;
    uint32_t* xl = xh + XW_WORDS;
    uint32_t* wh = xl + XW_WORDS;
    uint32_t* wl = wh + WW_WORDS;
    __shared__ float bs[CC];
    int tid=threadIdx.x, wid=tid>>5, lane=tid&31;
    if (NB>0 && tid<CC){ float bv=bias0[tid]; if (NB>1) bv+=bias1[tid]; bs[tid]=bv; }
    const float* ip[3]={in0,in1,in2};
    const float* wp[3]={w0,w1,w2};
    size_t bbase=(size_t)blockIdx.y*CC*NN;
    int nblk=blockIdx.x*128;
    int wm=wid&3, wn=wid>>2, g=lane>>2, tg=lane&3;
    float acc[8][4];
    #pragma unroll
    for (int t=0;t<8;t++){ acc[t][0]=0;acc[t][1]=0;acc[t][2]=0;acc[t][3]=0; }
    #pragma unroll 1
    for (int c=0;c<NC;c++){
        if (c) __syncthreads();
        {
            int c2=tid>>3, pp=(tid&7)*16;
            const float* r0 = ip[c] + bbase + nblk + (size_t)(2*c2)*NN;
            const float* r1 = r0 + NN;
            #pragma unroll
            for (int u=0;u<4;u++){
                float4 a=*(const float4*)(r0+pp+u*4);
                float4 b=*(const float4*)(r1+pp+u*4);
                stage_pair4(&xh[c2*XR+pp+u*4], &xl[c2*XR+pp+u*4], a, b);
            }
        }
        const float* wpc = wp[c];
        #pragma unroll
        for (int i=0;i<4;i++){
            int idx=tid+i*256; int o=idx>>4, c4=idx&15;
            float4 v=*(const float4*)(wpc + (size_t)o*wstride + c4*4);
            uint2 h,l;
            h.x=packbf(v.x,v.y); h.y=packbf(v.z,v.w);
            l.x=packbf(v.x-bfhi(v.x), v.y-bfhi(v.y));
            l.y=packbf(v.z-bfhi(v.z), v.w-bfhi(v.w));
            *(uint2*)&wh[o*WR+2*c4]=h;
            *(uint2*)&wl[o*WR+2*c4]=l;
        }
        __syncthreads();
        #pragma unroll
        for (int ks=0;ks<4;ks++){
            int k2=ks*8;
            int r0=(wm*16+g)*WR+k2+tg, r1=(wm*16+8+g)*WR+k2+tg;
            uint32_t Ah[4]={wh[r0],wh[r1],wh[r0+4],wh[r1+4]};
            uint32_t Al[4]={wl[r0],wl[r1],wl[r0+4],wl[r1+4]};
            #pragma unroll
            for (int t=0;t<8;t++){
                int n0=wn*64+t*8+g;
                int i0=(k2+tg)*XR+n0, i1=(k2+4+tg)*XR+n0;
                uint32_t b0h=xh[i0], b1h=xh[i1], b0l=xl[i0], b1l=xl[i1];
                mma16(acc[t],Ah,b0h,b1h);
                mma16(acc[t],Ah,b0l,b1l);
                mma16(acc[t],Al,b0h,b1h);
            }
        }
    }
    float* ob = outp + bbase + nblk;
    #pragma unroll
    for (int t=0;t<8;t++){
        int n0 = wn*64 + t*8 + 2*tg;
        int r0 = wm*16 + g;
        float2 v0 = make_float2(acc[t][0],acc[t][1]);
        float2 v1 = make_float2(acc[t][2],acc[t][3]);
        if (NB>0){ float b0v=bs[r0], b1v=bs[r0+8];
                   v0.x+=b0v; v0.y+=b0v; v1.x+=b1v; v1.y+=b1v; }
        if (GELU){ v0.x=gelu_f(v0.x); v0.y=gelu_f(v0.y); v1.x=gelu_f(v1.x); v1.y=gelu_f(v1.y); }
        *(float2*)(ob + (size_t)r0*NN + n0)     = v0;
        *(float2*)(ob + (size_t)(r0+8)*NN + n0) = v1;
    }
}

// =====================================================================
// Per-batch-weight conv: out = W1[b] @ in   (W1 from g_w1, 64x64 per batch)
// =====================================================================
__global__ __launch_bounds__(256,2)
void cmma_pb_k(const float* __restrict__ in, float* __restrict__ outp){
    extern __shared__ uint32_t smu[];
    uint32_t* xh = smu;
    uint32_t* xl = xh + XW_WORDS;
    uint32_t* wh = xl + XW_WORDS;
    uint32_t* wl = wh + WW_WORDS;
    int tid=threadIdx.x, wid=tid>>5, lane=tid&31;
    size_t bbase=(size_t)blockIdx.y*CC*NN;
    int nblk=blockIdx.x*128;
    const float* ib = in + bbase + nblk;
    {
        int c2=tid>>3, pp=(tid&7)*16;
        const float* r0 = ib + (size_t)(2*c2)*NN;
        const float* r1 = r0 + NN;
        #pragma unroll
        for (int u=0;u<4;u++){
            float4 a=*(const float4*)(r0+pp+u*4);
            float4 b=*(const float4*)(r1+pp+u*4);
            stage_pair4(&xh[c2*XR+pp+u*4], &xl[c2*XR+pp+u*4], a, b);
        }
    }
    {
        const float* wp = g_w1 + (size_t)blockIdx.y*CC*CC;
        #pragma unroll
        for (int i=0;i<4;i++){
            int idx=tid+i*256; int o=idx>>4, c4=idx&15;
            float4 v=*(const float4*)(wp + o*64 + c4*4);
            uint2 h,l;
            h.x=packbf(v.x,v.y); h.y=packbf(v.z,v.w);
            l.x=packbf(v.x-bfhi(v.x), v.y-bfhi(v.y));
            l.y=packbf(v.z-bfhi(v.z), v.w-bfhi(v.w));
            *(uint2*)&wh[o*WR+2*c4]=h;
            *(uint2*)&wl[o*WR+2*c4]=l;
        }
    }
    __syncthreads();
    int wm=wid&3, wn=wid>>2, g=lane>>2, tg=lane&3;
    float acc[8][4];
    #pragma unroll
    for (int t=0;t<8;t++){ acc[t][0]=0;acc[t][1]=0;acc[t][2]=0;acc[t][3]=0; }
    #pragma unroll
    for (int ks=0;ks<4;ks++){
        int k2=ks*8;
        int r0=(wm*16+g)*WR+k2+tg, r1=(wm*16+8+g)*WR+k2+tg;
        uint32_t Ah[4]={wh[r0],wh[r1],wh[r0+4],wh[r1+4]};
        uint32_t Al[4]={wl[r0],wl[r1],wl[r0+4],wl[r1+4]};
        #pragma unroll
        for (int t=0;t<8;t++){
            int n0=wn*64+t*8+g;
            int i0=(k2+tg)*XR+n0, i1=(k2+4+tg)*XR+n0;
            uint32_t b0h=xh[i0], b1h=xh[i1], b0l=xl[i0], b1l=xl[i1];
            mma16(acc[t],Ah,b0h,b1h);
            mma16(acc[t],Ah,b0l,b1l);
            mma16(acc[t],Al,b0h,b1h);
        }
    }
    float* ob = outp + bbase + nblk;
    #pragma unroll
    for (int t=0;t<8;t++){
        int n0 = wn*64 + t*8 + 2*tg;
        int r0 = wm*16 + g;
        *(float2*)(ob + (size_t)r0*NN + n0)     = make_float2(acc[t][0],acc[t][1]);
        *(float2*)(ob + (size_t)(r0+8)*NN + n0) = make_float2(acc[t][2],acc[t][3]);
    }
}

// =====================================================================
// Precompute M = Wq^T @ Wk for row(0)/col(1), packed bf16 hi/lo
// =====================================================================
__global__ void mprep_k(const float* __restrict__ rq, const float* __restrict__ rk,
                        const float* __restrict__ cq, const float* __restrict__ ck){
    int d = blockIdx.x, tid = threadIdx.x;
    const float* Wq = d ? cq : rq;
    const float* Wk = d ? ck : rk;
    __shared__ float sq[CC*CC], sk[CC*CC], smm[CC*CC];
    for (int i=tid;i<CC*CC;i+=256){ sq[i]=Wq[i]; sk[i]=Wk[i]; }
    __syncthreads();
    for (int e=tid;e<CC*CC;e+=256){
        int a=e>>6, b=e&63;
        float s=0.f;
        #pragma unroll
        for (int c=0;c<CC;c++) s += sq[c*64+a]*sk[c*64+b];
        smm[a*64+b]=s;
    }
    __syncthreads();
    for (int e=tid;e<2048;e+=256){
        int bp=e>>6, a=e&63;
        float v0=smm[a*64+2*bp], v1=smm[a*64+2*bp+1];
        g_mh[d][bp*64+a]=packbf(bfhi(v0),bfhi(v1));
        g_ml[d][bp*64+a]=packbf(v0-bfhi(v0), v1-bfhi(v1));
    }
}

// ---------------- per-batch W1 = att_p_w @ blockdiag(attn) ----------------
__global__ void wcomb1_k(const float* __restrict__ att_p_w){
    int b = blockIdx.x, tid=threadIdx.x;
    __shared__ float sA[NHEADS*32*32];
    __shared__ float sP[CC*CC];
    for (int i=tid;i<NHEADS*32*32;i+=256) sA[i]=g_attn[b*NHEADS*32*32+i];
    for (int i=tid;i<CC*CC;i+=256) sP[i]=att_p_w[i];
    __syncthreads();
    for (int i=tid;i<CC*CC;i+=256){
        int o=i>>6, m=i&63; int g=m>>5, d=m&31;
        float s=0.f;
        #pragma unroll
        for (int c=0;c<32;c++) s += sP[o*64+g*32+c]*sA[g*1024+c*32+d];
        g_w1[(size_t)b*CC*CC + i]=s;
    }
}

// =====================================================================
// Fused row attention with algebraic Q/K elimination (unchanged from R14)
// =====================================================================
#define SL 192
#define SSP 204
#define KPR 72
#define VPR 36
#define QR 200
#define FA_SMEM ((SL*SSP + 2*32*QR + 2*32*KPR + SL)*4)   // 227072 B

__global__ __launch_bounds__(256,1)
void fattn_k(const float* __restrict__ X,
             const uint32_t* __restrict__ mh, const uint32_t* __restrict__ ml,
             const float* __restrict__ V, const float* __restrict__ res,
             const float* __restrict__ gamma_p, float* __restrict__ out){
    extern __shared__ float sm[];
    float*    sS = sm;
    uint32_t* qh = (uint32_t*)(sS + SL*SSP);
    uint32_t* ql = qh + 32*QR;
    uint32_t* kvh= ql + 32*QR;
    uint32_t* kvl= kvh + 32*KPR;
    float*    sL = (float*)(kvl + 32*KPR);
    int tid=threadIdx.x, wid=tid>>5, lane=tid&31;
    int b = blockIdx.x / HH, r = blockIdx.x % HH;
    size_t base = (size_t)b*CC*NN + (size_t)r*WW;
    {
        int c2=tid>>3, pp=(tid&7)*24;
        const float* r0 = X + base + (size_t)(2*c2)*NN;
        const float* r1 = r0 + NN;
        #pragma unroll
        for (int u=0;u<6;u++){
            float4 a=*(const float4*)(r0+pp+u*4);
            float4 b4=*(const float4*)(r1+pp+u*4);
            stage_pair4(&qh[c2*QR+pp+u*4], &ql[c2*QR+pp+u*4], a, b4);
        }
    }
    __syncthreads();
    int wm = wid&1, wn = wid>>1;
    int g = lane>>2, tg = lane&3;
    float acc[12][4];
    for (int jt=0;jt<3;jt++){
        if (jt) __syncthreads();
        {
            int ymt = wid&3, ywn = wid>>2;
            int jg0 = jt*64 + ymt*16;
            float yac[4][4];
            #pragma unroll
            for (int u=0;u<4;u++){ yac[u][0]=0;yac[u][1]=0;yac[u][2]=0;yac[u][3]=0; }
            #pragma unroll
            for (int kc=0;kc<4;kc++){
                int k2=kc*8;
                uint32_t Ah[4],Al[4];
                Ah[0]=qh[(k2+tg)*QR + jg0+g];   Ah[1]=qh[(k2+tg)*QR + jg0+8+g];
                Ah[2]=qh[(k2+4+tg)*QR + jg0+g]; Ah[3]=qh[(k2+4+tg)*QR + jg0+8+g];
                Al[0]=ql[(k2+tg)*QR + jg0+g];   Al[1]=ql[(k2+tg)*QR + jg0+8+g];
                Al[2]=ql[(k2+4+tg)*QR + jg0+g]; Al[3]=ql[(k2+4+tg)*QR + jg0+8+g];
                #pragma unroll
                for (int u=0;u<4;u++){
                    int n0 = (ywn*4+u)*8;
                    uint32_t b0h = mh[(k2+tg)*64 + n0+g],  b1h = mh[(k2+4+tg)*64 + n0+g];
                    uint32_t b0l = ml[(k2+tg)*64 + n0+g],  b1l = ml[(k2+4+tg)*64 + n0+g];
                    mma16(yac[u],Ah,b0h,b1h);
                    mma16(yac[u],Ah,b0l,b1l);
                    mma16(yac[u],Al,b0h,b1h);
                }
            }
            #pragma unroll
            for (int u=0;u<4;u++){
                int ap = (ywn*4+u)*4 + tg;
                int jl = ymt*16 + g;
                float d0=yac[u][0], d1=yac[u][1], d2=yac[u][2], d3=yac[u][3];
                kvh[ap*KPR + jl]   = packbf(bfhi(d0), bfhi(d1));
                kvl[ap*KPR + jl]   = packbf(d0-bfhi(d0), d1-bfhi(d1));
                kvh[ap*KPR + jl+8] = packbf(bfhi(d2), bfhi(d3));
                kvl[ap*KPR + jl+8] = packbf(d2-bfhi(d2), d3-bfhi(d3));
            }
        }
        __syncthreads();
        #pragma unroll
        for (int t=0;t<12;t++){acc[t][0]=0;acc[t][1]=0;acc[t][2]=0;acc[t][3]=0;}
        #pragma unroll
        for (int kc=0;kc<4;kc++){
            int k2=kc*8;
            uint32_t Ah[2][4], Al[2][4];
            #pragma unroll
            for (int mt=0;mt<2;mt++){
                int m0 = wm*32+mt*16;
                #pragma unroll
                for (int w=0;w<4;w++){
                    int c2p = k2 + tg + (w>>1)*4;
                    int row = m0 + g + (w&1)*8;
                    Ah[mt][w]=kvh[c2p*KPR+row];
                    Al[mt][w]=kvl[c2p*KPR+row];
                }
            }
            #pragma unroll
            for (int nt=0;nt<6;nt++){
                int n0 = wn*48+nt*8+g;
                uint32_t b0h=qh[(k2+tg)*QR+n0],   b1h=qh[(k2+4+tg)*QR+n0];
                uint32_t b0l=ql[(k2+tg)*QR+n0],   b1l=ql[(k2+4+tg)*QR+n0];
                #pragma unroll
                for (int mt=0;mt<2;mt++){
                    float* a = acc[mt*6+nt];
                    mma16(a,Ah[mt],b0h,b1h);
                    mma16(a,Ah[mt],b0l,b1l);
                    mma16(a,Al[mt],b0h,b1h);
                }
            }
        }
        #pragma unroll
        for (int mt=0;mt<2;mt++){
            int j0 = jt*64 + wm*32 + mt*16;
            #pragma unroll
            for (int nt=0;nt<6;nt++){
                int n0 = wn*48+nt*8;
                float* a = acc[mt*6+nt];
                *(float2*)&sS[(j0+g)*SSP + n0+2*tg]   = make_float2(a[0],a[1]);
                *(float2*)&sS[(j0+8+g)*SSP + n0+2*tg] = make_float2(a[2],a[3]);
            }
        }
    }
    __syncthreads();
    if (tid < SL){
        int i = tid;
        float m = -3.4e38f;
        #pragma unroll 8
        for (int j=0;j<SL;j++) m = fmaxf(m, sS[j*SSP+i]);
        float s = 0.f;
        #pragma unroll 4
        for (int j2=0;j2<SL/2;j2++){
            float e0 = __expf(sS[(2*j2)*SSP+i]-m);
            float e1 = __expf(sS[(2*j2+1)*SSP+i]-m);
            s += e0+e1;
            sS[(2*j2)*SSP+i]   = __uint_as_float(packbf(e0,e1));
            sS[(2*j2+1)*SSP+i] = __uint_as_float(packbf(e0-bfhi(e0), e1-bfhi(e1)));
        }
        sL[i] = 1.f/s;
    }
    #pragma unroll
    for (int t=0;t<12;t++){acc[t][0]=0;acc[t][1]=0;acc[t][2]=0;acc[t][3]=0;}
    for (int jt=0;jt<3;jt++){
        __syncthreads();
        {
            int c = tid>>2, j20 = (tid&3)*8;
            const float4* src = (const float4*)(V + base + (size_t)c*NN + jt*64 + j20*2);
            #pragma unroll
            for (int u=0;u<4;u++){
                float4 v = src[u];
                uint2 h,l;
                h.x=packbf(v.x,v.y); h.y=packbf(v.z,v.w);
                l.x=packbf(v.x-bfhi(v.x), v.y-bfhi(v.y));
                l.y=packbf(v.z-bfhi(v.z), v.w-bfhi(v.w));
                *(uint2*)&kvh[c*VPR + j20 + 2*u] = h;
                *(uint2*)&kvl[c*VPR + j20 + 2*u] = l;
            }
        }
        __syncthreads();
        #pragma unroll
        for (int kc=0;kc<4;kc++){
            uint32_t Ah[2][4], Al[2][4];
            #pragma unroll
            for (int mt=0;mt<2;mt++){
                int m0 = wm*32+mt*16;
                #pragma unroll
                for (int w=0;w<4;w++){
                    int row = m0 + g + (w&1)*8;
                    int jp  = kc*8 + tg + (w>>1)*4;
                    Ah[mt][w]=kvh[row*VPR+jp];
                    Al[mt][w]=kvl[row*VPR+jp];
                }
            }
            int j2g = jt*32 + kc*8;
            #pragma unroll
            for (int nt=0;nt<6;nt++){
                int n0 = wn*48+nt*8+g;
                uint32_t b0h=__float_as_uint(sS[(2*(j2g+tg))*SSP+n0]);
                uint32_t b0l=__float_as_uint(sS[(2*(j2g+tg)+1)*SSP+n0]);
                uint32_t b1h=__float_as_uint(sS[(2*(j2g+4+tg))*SSP+n0]);
                uint32_t b1l=__float_as_uint(sS[(2*(j2g+4+tg)+1)*SSP+n0]);
                #pragma unroll
                for (int mt=0;mt<2;mt++){
                    float* a = acc[mt*6+nt];
                    mma16(a,Ah[mt],b0h,b1h);
                    mma16(a,Ah[mt],b0l,b1l);
                    mma16(a,Al[mt],b0h,b1h);
                }
            }
        }
    }
    float gm = gamma_p[0];
    #pragma unroll
    for (int mt=0;mt<2;mt++){
        int m0 = wm*32+mt*16;
        #pragma unroll
        for (int nt=0;nt<6;nt++){
            int n0 = wn*48+nt*8 + 2*tg;
            float il0 = sL[n0], il1 = sL[n0+1];
            float* a = acc[mt*6+nt];
            float2 r0 = *(const float2*)(res + base + (size_t)(m0+g)*NN + n0);
            float2 r1 = *(const float2*)(res + base + (size_t)(m0+8+g)*NN + n0);
            *(float2*)(out + base + (size_t)(m0+g)*NN + n0) =
                make_float2(gm*a[0]*il0 + r0.x, gm*a[1]*il1 + r0.y);
            *(float2*)(out + base + (size_t)(m0+8+g)*NN + n0) =
                make_float2(gm*a[2]*il0 + r1.x, gm*a[3]*il1 + r1.y);
        }
    }
}

// ---------------- depthwise 3x3: tiled, zero-padded smem, no per-pixel ALU ----------------
#define DWROWS 8
__global__ __launch_bounds__(192)
void dwconv_k(const float* __restrict__ in, const float* __restrict__ w,
              const float* __restrict__ bias, float* __restrict__ out){
    __shared__ float sm[(DWROWS+2)*194];
    int bc = blockIdx.y;
    int y0 = blockIdx.x*DWROWS;
    int c  = bc % CC;
    const float* ip = in + (size_t)bc*NN;
    float* op = out + (size_t)bc*NN;
    int x = threadIdx.x;
    // load weights/bias (uniform)
    float wr[9];
    #pragma unroll
    for (int i=0;i<9;i++) wr[i]=w[c*9+i];
    float bv = bias[c];
    // stage (DWROWS+2) x 194 with zero padding
    for (int i=threadIdx.x; i<(DWROWS+2)*194; i+=192){
        int row=i/194, col=i%194;
        int gy=y0+row-1, gx=col-1;
        float v = 0.f;
        if ((unsigned)gy < HH && (unsigned)gx < WW) v = ip[(size_t)gy*WW+gx];
        sm[i]=v;
    }
    __syncthreads();
    #pragma unroll
    for (int r=0;r<DWROWS;r++){
        const float* s0=&sm[(r+0)*194 + x];
        const float* s1=&sm[(r+1)*194 + x];
        const float* s2=&sm[(r+2)*194 + x];
        float acc = bv
            + wr[0]*s0[0] + wr[1]*s0[1] + wr[2]*s0[2]
            + wr[3]*s1[0] + wr[4]*s1[1] + wr[5]*s1[2]
            + wr[6]*s2[0] + wr[7]*s2[1] + wr[8]*s2[2];
        op[(size_t)(y0+r)*WW + x] = gelu_f(acc);
    }
}

// ---------------- transpose [b,c,H,W] -> [b,c,W,H] ----------------
__global__ void transpose_k(const float* __restrict__ in, float* __restrict__ out){
    __shared__ float t[32][33];
    const float* ib = in + (size_t)blockIdx.z*NN;
    float* ob = out + (size_t)blockIdx.z*NN;
    int x = blockIdx.x*32 + threadIdx.x;
    #pragma unroll
    for (int k=0;k<32;k+=8)
        t[threadIdx.y+k][threadIdx.x] = ib[(size_t)(blockIdx.y*32+threadIdx.y+k)*WW + x];
    __syncthreads();
    int x2 = blockIdx.y*32 + threadIdx.x;
    #pragma unroll
    for (int k=0;k<32;k+=8)
        ob[(size_t)(blockIdx.x*32+threadIdx.y+k)*HH + x2] = t[threadIdx.x][threadIdx.y+k];
}

__global__ void zero_attn_k(){
    int i = blockIdx.x*blockDim.x+threadIdx.x;
    if (i < BB*NHEADS*32*32) g_attn[i]=0.f;
    if (i < 2*BB*CC) g_norm[i]=0.f;
}

// ---------------- channel-attn gram (chunked atomics) + fused q/k norms ----------------
#define NCHUNK 32
#define CHUNK (NN/NCHUNK)
__global__ void gram_k(const float* __restrict__ q, const float* __restrict__ k){
    int bg = blockIdx.x; int b=bg/NHEADS, g=bg%NHEADS;
    int n0 = blockIdx.y*CHUNK;
    __shared__ float qs[64][33], ks[64][33];
    int c = threadIdx.x>>3, dg = threadIdx.x&7;
    float a0=0,a1=0,a2=0,a3=0;
    float nq=0.f, nk0=0.f, nk1=0.f, nk2=0.f, nk3=0.f;
    const float* qb = q + ((size_t)(b*CC + g*32))*NN + n0;
    const float* kb = k + ((size_t)(b*CC + g*32))*NN + n0;
    for (int tt=0;tt<CHUNK;tt+=64){
        __syncthreads();
        for (int e=threadIdx.x;e<32*64;e+=256){
            int cc=e>>6, t=e&63;
            qs[t][cc]=qb[(size_t)cc*NN + tt + t];
            ks[t][cc]=kb[(size_t)cc*NN + tt + t];
        }
        __syncthreads();
        #pragma unroll 8
        for (int t=0;t<64;t++){
            float qv=qs[t][c];
            float k0=ks[t][dg], k1=ks[t][dg+8], k2=ks[t][dg+16], k3=ks[t][dg+24];
            a0+=qv*k0; a1+=qv*k1; a2+=qv*k2; a3+=qv*k3;
            if (dg==0) nq += qv*qv;
            if (c==0){ nk0+=k0*k0; nk1+=k1*k1; nk2+=k2*k2; nk3+=k3*k3; }
        }
    }
    float* ab = g_attn + ((size_t)(bg*32+c))*32;
    atomicAdd(&ab[dg],a0);    atomicAdd(&ab[dg+8],a1);
    atomicAdd(&ab[dg+16],a2); atomicAdd(&ab[dg+24],a3);
    if (dg==0) atomicAdd(&g_norm[b*CC + g*32 + c], nq);
    if (c==0){
        float* nb = g_norm + BB*CC + b*CC + g*32;
        atomicAdd(&nb[dg],nk0);    atomicAdd(&nb[dg+8],nk1);
        atomicAdd(&nb[dg+16],nk2); atomicAdd(&nb[dg+24],nk3);
    }
}

// ---------------- channel-attn softmax ----------------
__global__ void chsm_k(const float* __restrict__ temp){
    int bg = blockIdx.x; int b=bg/NHEADS, g=bg%NHEADS;
    int c = threadIdx.x>>5, d = threadIdx.x&31;
    float nq = fmaxf(sqrtf(g_norm[b*CC + g*32 + c]), 1e-12f);
    float nk = fmaxf(sqrtf(g_norm[BB*CC + b*CC + g*32 + d]), 1e-12f);
    int idx = (bg*32+c)*32+d;
    float v = g_attn[idx]/(nq*nk)*temp[g];
    float m=v;
    #pragma unroll
    for (int o=16;o;o>>=1) m=fmaxf(m,__shfl_xor_sync(0xffffffffu,m,o));
    float e=expf(v-m), s=e;
    #pragma unroll
    for (int o=16;o;o>>=1) s+=__shfl_xor_sync(0xffffffffu,s,o);
    g_attn[idx]=e/s;
}

// =======================================================================
extern "C" void kernel_launch(void* const* d_in, const int* in_sizes, int n_in,
                              void* d_out, int out_size){
    const float* x      =(const float*)d_in[0];
    const float* pw_w   =(const float*)d_in[1];
    const float* dw_w   =(const float*)d_in[2];
    const float* dw_b   =(const float*)d_in[3];
    const float* conv2_w=(const float*)d_in[4];
    const float* conv2_b=(const float*)d_in[5];
    const float* conv0_w=(const float*)d_in[6];
    const float* conv0_b=(const float*)d_in[7];
    const float* att_q_w=(const float*)d_in[8];
    const float* att_k_w=(const float*)d_in[9];
    const float* att_v_w=(const float*)d_in[10];
    const float* att_p_w=(const float*)d_in[11];
    const float* temp   =(const float*)d_in[12];
    const float* row_q_w=(const float*)d_in[13];
    const float* row_k_w=(const float*)d_in[14];
    const float* row_v_w=(const float*)d_in[15];
    const float* row_g  =(const float*)d_in[16];
    const float* col_q_w=(const float*)d_in[17];
    const float* col_k_w=(const float*)d_in[18];
    const float* col_v_w=(const float*)d_in[19];
    const float* col_g  =(const float*)d_in[20];
    const float* conv_w =(const float*)d_in[21];
    const float* conv_b =(const float*)d_in[22];
    float* out=(float*)d_out;

    float *t0,*t1,*x1b,*q,*k,*v,*o1,*o2,*o3;
    uint32_t *mh,*ml;
    cudaGetSymbolAddress((void**)&t0,  g_t0);
    cudaGetSymbolAddress((void**)&t1,  g_t1);
    cudaGetSymbolAddress((void**)&x1b, g_x1);
    cudaGetSymbolAddress((void**)&q,   g_q);
    cudaGetSymbolAddress((void**)&k,   g_k);
    cudaGetSymbolAddress((void**)&v,   g_v);
    cudaGetSymbolAddress((void**)&o1,  g_o1);
    cudaGetSymbolAddress((void**)&o2,  g_o2);
    cudaGetSymbolAddress((void**)&o3,  g_o3);
    cudaGetSymbolAddress((void**)&mh,  g_mh);
    cudaGetSymbolAddress((void**)&ml,  g_ml);

    const int SM_Q1 = (2*XW_WORDS + 1*2*WW_WORDS)*4;   // 53248
    const int SM_Q3 = (2*XW_WORDS + 3*2*WW_WORDS)*4;   // 90112
    const int SM_CM = (2*XW_WORDS + 2*WW_WORDS)*4;     // 53248
    cudaFuncSetAttribute(qkvmma_k<1>, cudaFuncAttributeMaxDynamicSharedMemorySize, SM_Q1);
    cudaFuncSetAttribute(qkvmma_k<3>, cudaFuncAttributeMaxDynamicSharedMemorySize, SM_Q3);
    cudaFuncSetAttribute(cmma_k<2,2,false>, cudaFuncAttributeMaxDynamicSharedMemorySize, SM_CM);
    cudaFuncSetAttribute(cmma_k<3,1,true>,  cudaFuncAttributeMaxDynamicSharedMemorySize, SM_CM);
    cudaFuncSetAttribute(cmma_pb_k, cudaFuncAttributeMaxDynamicSharedMemorySize, SM_CM);
    cudaFuncSetAttribute(fattn_k, cudaFuncAttributeMaxDynamicSharedMemorySize, FA_SMEM);

    dim3 mg(NN/128, BB);

    // ---- prologue ----
    zero_attn_k<<<32,256>>>();
    mprep_k<<<2,256>>>(row_q_w,row_k_w,col_q_w,col_k_w);

    // ---- BSConvU + skip -> x1 ----
    qkvmma_k<1><<<mg,256,SM_Q1>>>(x, pw_w,nullptr,nullptr, t0,nullptr,nullptr);
    dwconv_k<<<dim3(HH/DWROWS, BB*CC),192>>>(t0, dw_w, dw_b, t1);
    cmma_k<2,2,false><<<mg,256,SM_CM>>>(t1,x,nullptr, conv2_w,conv0_w,nullptr, 64,
                                        conv2_b,conv0_b, x1b);

    // ---- channel self-attention: qkv, gram(+norm), softmax, W1-fold, o1 ----
    qkvmma_k<3><<<mg,256,SM_Q3>>>(x1b, att_q_w,att_k_w,att_v_w, q,k,v);
    gram_k<<<dim3(BB*NHEADS,NCHUNK),256>>>(q,k);
    chsm_k<<<BB*NHEADS,1024>>>(temp);
    wcomb1_k<<<BB,256>>>(att_p_w);
    cmma_pb_k<<<mg,256,SM_CM>>>(v, o1);

    // ---- row attention -> o2 (Q/K folded into fattn via M) ----
    qkvmma_k<1><<<mg,256,SM_Q1>>>(o1, row_v_w,nullptr,nullptr, v,nullptr,nullptr);
    fattn_k<<<BB*HH,256,FA_SMEM>>>(x1b, mh, ml, v, x1b, row_g, o2);

    // ---- col attention (transposed) -> o3 ----
    transpose_k<<<dim3(6,6,BB*CC),dim3(32,8)>>>(x1b, t1);
    transpose_k<<<dim3(6,6,BB*CC),dim3(32,8)>>>(o1,  t0);
    qkvmma_k<1><<<mg,256,SM_Q1>>>(t0, col_v_w,nullptr,nullptr, v,nullptr,nullptr);
    fattn_k<<<BB*WW,256,FA_SMEM>>>(t1, mh+2048, ml+2048, v, t1, col_g, q);
    transpose_k<<<dim3(6,6,BB*CC),dim3(32,8)>>>(q, o3);

    // ---- fuse ----
    cmma_k<3,1,true><<<mg,256,SM_CM>>>(o1,o2,o3, conv_w,conv_w+64,conv_w+128, 192,
                                       conv_b,nullptr, out);
}

// round 16
// speedup vs baseline: 1.1635x; 1.0433x over previous
#include <cuda_runtime.h>
#include <cuda_bf16.h>
#include <math.h>
#include <stdint.h>

#define BB 4
#define CC 64
#define HH 192
#define WW 192
#define NN (HH*WW)          // 36864
#define PP (BB*NN)
#define NHEADS 2

// ---------------- scratch ----------------
__device__ float g_t0[BB*CC*NN];
__device__ float g_t1[BB*CC*NN];
__device__ float g_x1[BB*CC*NN];
__device__ float g_q [BB*CC*NN];
__device__ float g_k [BB*CC*NN];
__device__ float g_v [BB*CC*NN];
__device__ float g_o1[BB*CC*NN];
__device__ float g_o2[BB*CC*NN];
__device__ float g_o3[BB*CC*NN];
__device__ float g_norm[2*BB*CC];
__device__ float g_attn[BB*NHEADS*32*32];
__device__ float g_w1[BB*CC*CC];     // W1 = att_p_w @ BD(attn) per batch
__device__ uint32_t g_mh[2][2048];   // packed M = Wq^T Wk (dir 0=row,1=col)
__device__ uint32_t g_ml[2][2048];

__device__ __forceinline__ float gelu_f(float v){
    return 0.5f*v*(1.f+erff(v*0.70710678118654752f));
}
__device__ __forceinline__ uint32_t packbf(float lo, float hi){
    uint32_t r; asm("cvt.rn.bf16x2.f32 %0, %1, %2;" : "=r"(r) : "f"(hi), "f"(lo)); return r;
}
__device__ __forceinline__ float bfhi(float v){
    return __bfloat162float(__float2bfloat16(v));
}
__device__ __forceinline__ void mma16(float* d, const uint32_t* a, uint32_t b0, uint32_t b1){
    asm("mma.sync.aligned.m16n8k16.row.col.f32.bf16.bf16.f32 "
        "{%0,%1,%2,%3},{%4,%5,%6,%7},{%8,%9},{%0,%1,%2,%3};"
        : "+f"(d[0]),"+f"(d[1]),"+f"(d[2]),"+f"(d[3])
        : "r"(a[0]),"r"(a[1]),"r"(a[2]),"r"(a[3]),"r"(b0),"r"(b1));
}
__device__ __forceinline__ void stage_pair4(uint32_t* hp, uint32_t* lp, float4 a, float4 b){
    uint4 h, l;
    h.x=packbf(a.x,b.x); h.y=packbf(a.y,b.y); h.z=packbf(a.z,b.z); h.w=packbf(a.w,b.w);
    l.x=packbf(a.x-bfhi(a.x), b.x-bfhi(b.x));
    l.y=packbf(a.y-bfhi(a.y), b.y-bfhi(b.y));
    l.z=packbf(a.z-bfhi(a.z), b.z-bfhi(b.z));
    l.w=packbf(a.w-bfhi(a.w), b.w-bfhi(b.w));
    *(uint4*)hp = h; *(uint4*)lp = l;
}

#define XR 136
#define WR 36
#define XW_WORDS (32*XR)
#define WW_WORDS (64*WR)

// =====================================================================
// QKV-style bf16-split mma conv: NS weight sets sharing one input. K=64.
// =====================================================================
template<int NS>
__global__ __launch_bounds__(256, NS==1?2:1)
void qkvmma_k(const float* __restrict__ in,
              const float* __restrict__ w0,const float* __restrict__ w1,const float* __restrict__ w2,
              float* __restrict__ p0,float* __restrict__ p1,float* __restrict__ p2){
    extern __shared__ uint32_t smu[];
    uint32_t* xh = smu;
    uint32_t* xl = xh + XW_WORDS;
    uint32_t* wsm= xl + XW_WORDS;
    int tid=threadIdx.x, wid=tid>>5, lane=tid&31;
    const float* wptr[3]={w0,w1,w2};
    float* optr[3]={p0,p1,p2};
    size_t bbase=(size_t)blockIdx.y*CC*NN;
    int nblk=blockIdx.x*128;
    const float* ib = in + bbase + nblk;
    {
        int c2=tid>>3, pp=(tid&7)*16;
        const float* r0 = ib + (size_t)(2*c2)*NN;
        const float* r1 = r0 + NN;
        #pragma unroll
        for (int u=0;u<4;u++){
            float4 a=*(const float4*)(r0+pp+u*4);
            float4 b=*(const float4*)(r1+pp+u*4);
            stage_pair4(&xh[c2*XR+pp+u*4], &xl[c2*XR+pp+u*4], a, b);
        }
    }
    #pragma unroll
    for (int s=0;s<NS;s++){
        const float* wp=wptr[s];
        uint32_t* wh = wsm + s*2*WW_WORDS;
        uint32_t* wl = wh + WW_WORDS;
        #pragma unroll
        for (int i=0;i<4;i++){
            int idx=tid+i*256; int o=idx>>4, c4=idx&15;
            float4 v=*(const float4*)(wp + o*64 + c4*4);
            uint2 h,l;
            h.x=packbf(v.x,v.y); h.y=packbf(v.z,v.w);
            l.x=packbf(v.x-bfhi(v.x), v.y-bfhi(v.y));
            l.y=packbf(v.z-bfhi(v.z), v.w-bfhi(v.w));
            *(uint2*)&wh[o*WR+2*c4]=h;
            *(uint2*)&wl[o*WR+2*c4]=l;
        }
    }
    __syncthreads();
    int wm=wid&3, wn=wid>>2, g=lane>>2, tg=lane&3;
    float acc[NS][8][4];
    #pragma unroll
    for (int s=0;s<NS;s++)
        #pragma unroll
        for (int t=0;t<8;t++)
            #pragma unroll
            for (int e=0;e<4;e++) acc[s][t][e]=0.f;
    #pragma unroll
    for (int ks=0;ks<4;ks++){
        int k2=ks*8;
        uint32_t B0h[8],B1h[8],B0l[8],B1l[8];
        #pragma unroll
        for (int t=0;t<8;t++){
            int n0=wn*64+t*8+g;
            int i0=(k2+tg)*XR+n0, i1=(k2+4+tg)*XR+n0;
            B0h[t]=xh[i0]; B1h[t]=xh[i1];
            B0l[t]=xl[i0]; B1l[t]=xl[i1];
        }
        #pragma unroll
        for (int s=0;s<NS;s++){
            const uint32_t* wh = wsm + s*2*WW_WORDS;
            const uint32_t* wl = wh + WW_WORDS;
            int r0=(wm*16+g)*WR+k2+tg, r1=(wm*16+8+g)*WR+k2+tg;
            uint32_t Ah[4]={wh[r0],wh[r1],wh[r0+4],wh[r1+4]};
            uint32_t Al[4]={wl[r0],wl[r1],wl[r0+4],wl[r1+4]};
            #pragma unroll
            for (int t=0;t<8;t++){
                mma16(acc[s][t],Ah,B0h[t],B1h[t]);
                mma16(acc[s][t],Ah,B0l[t],B1l[t]);
                mma16(acc[s][t],Al,B0h[t],B1h[t]);
            }
        }
    }
    #pragma unroll
    for (int s=0;s<NS;s++){
        float* ob = optr[s] + bbase + nblk;
        #pragma unroll
        for (int t=0;t<8;t++){
            int n0 = wn*64 + t*8 + 2*tg;
            int r0 = wm*16 + g;
            *(float2*)(ob + (size_t)r0*NN + n0)     = make_float2(acc[s][t][0],acc[s][t][1]);
            *(float2*)(ob + (size_t)(r0+8)*NN + n0) = make_float2(acc[s][t][2],acc[s][t][3]);
        }
    }
}

// =====================================================================
// K-concat bf16-split mma conv
// =====================================================================
template<int NC,int NB,bool GELU>
__global__ __launch_bounds__(256,2)
void cmma_k(const float* __restrict__ in0,const float* __restrict__ in1,const float* __restrict__ in2,
            const float* __restrict__ w0,const float* __restrict__ w1,const float* __restrict__ w2,
            int wstride,
            const float* __restrict__ bias0,const float* __restrict__ bias1,
            float* __restrict__ outp){
    extern __shared__ uint32_t smu[];
    uint32_t* xh = smu;
    uint32_t* xl = xh + XW_WORDS;
    uint32_t* wh = xl + XW_WORDS;
    uint32_t* wl = wh + WW_WORDS;
    __shared__ float bs[CC];
    int tid=threadIdx.x, wid=tid>>5, lane=tid&31;
    if (NB>0 && tid<CC){ float bv=bias0[tid]; if (NB>1) bv+=bias1[tid]; bs[tid]=bv; }
    const float* ip[3]={in0,in1,in2};
    const float* wp[3]={w0,w1,w2};
    size_t bbase=(size_t)blockIdx.y*CC*NN;
    int nblk=blockIdx.x*128;
    int wm=wid&3, wn=wid>>2, g=lane>>2, tg=lane&3;
    float acc[8][4];
    #pragma unroll
    for (int t=0;t<8;t++){ acc[t][0]=0;acc[t][1]=0;acc[t][2]=0;acc[t][3]=0; }
    #pragma unroll 1
    for (int c=0;c<NC;c++){
        if (c) __syncthreads();
        {
            int c2=tid>>3, pp=(tid&7)*16;
            const float* r0 = ip[c] + bbase + nblk + (size_t)(2*c2)*NN;
            const float* r1 = r0 + NN;
            #pragma unroll
            for (int u=0;u<4;u++){
                float4 a=*(const float4*)(r0+pp+u*4);
                float4 b=*(const float4*)(r1+pp+u*4);
                stage_pair4(&xh[c2*XR+pp+u*4], &xl[c2*XR+pp+u*4], a, b);
            }
        }
        const float* wpc = wp[c];
        #pragma unroll
        for (int i=0;i<4;i++){
            int idx=tid+i*256; int o=idx>>4, c4=idx&15;
            float4 v=*(const float4*)(wpc + (size_t)o*wstride + c4*4);
            uint2 h,l;
            h.x=packbf(v.x,v.y); h.y=packbf(v.z,v.w);
            l.x=packbf(v.x-bfhi(v.x), v.y-bfhi(v.y));
            l.y=packbf(v.z-bfhi(v.z), v.w-bfhi(v.w));
            *(uint2*)&wh[o*WR+2*c4]=h;
            *(uint2*)&wl[o*WR+2*c4]=l;
        }
        __syncthreads();
        #pragma unroll
        for (int ks=0;ks<4;ks++){
            int k2=ks*8;
            int r0=(wm*16+g)*WR+k2+tg, r1=(wm*16+8+g)*WR+k2+tg;
            uint32_t Ah[4]={wh[r0],wh[r1],wh[r0+4],wh[r1+4]};
            uint32_t Al[4]={wl[r0],wl[r1],wl[r0+4],wl[r1+4]};
            #pragma unroll
            for (int t=0;t<8;t++){
                int n0=wn*64+t*8+g;
                int i0=(k2+tg)*XR+n0, i1=(k2+4+tg)*XR+n0;
                uint32_t b0h=xh[i0], b1h=xh[i1], b0l=xl[i0], b1l=xl[i1];
                mma16(acc[t],Ah,b0h,b1h);
                mma16(acc[t],Ah,b0l,b1l);
                mma16(acc[t],Al,b0h,b1h);
            }
        }
    }
    float* ob = outp + bbase + nblk;
    #pragma unroll
    for (int t=0;t<8;t++){
        int n0 = wn*64 + t*8 + 2*tg;
        int r0 = wm*16 + g;
        float2 v0 = make_float2(acc[t][0],acc[t][1]);
        float2 v1 = make_float2(acc[t][2],acc[t][3]);
        if (NB>0){ float b0v=bs[r0], b1v=bs[r0+8];
                   v0.x+=b0v; v0.y+=b0v; v1.x+=b1v; v1.y+=b1v; }
        if (GELU){ v0.x=gelu_f(v0.x); v0.y=gelu_f(v0.y); v1.x=gelu_f(v1.x); v1.y=gelu_f(v1.y); }
        *(float2*)(ob + (size_t)r0*NN + n0)     = v0;
        *(float2*)(ob + (size_t)(r0+8)*NN + n0) = v1;
    }
}

// =====================================================================
// Per-batch-weight conv: out = W1[b] @ in
// =====================================================================
__global__ __launch_bounds__(256,2)
void cmma_pb_k(const float* __restrict__ in, float* __restrict__ outp){
    extern __shared__ uint32_t smu[];
    uint32_t* xh = smu;
    uint32_t* xl = xh + XW_WORDS;
    uint32_t* wh = xl + XW_WORDS;
    uint32_t* wl = wh + WW_WORDS;
    int tid=threadIdx.x, wid=tid>>5, lane=tid&31;
    size_t bbase=(size_t)blockIdx.y*CC*NN;
    int nblk=blockIdx.x*128;
    const float* ib = in + bbase + nblk;
    {
        int c2=tid>>3, pp=(tid&7)*16;
        const float* r0 = ib + (size_t)(2*c2)*NN;
        const float* r1 = r0 + NN;
        #pragma unroll
        for (int u=0;u<4;u++){
            float4 a=*(const float4*)(r0+pp+u*4);
            float4 b=*(const float4*)(r1+pp+u*4);
            stage_pair4(&xh[c2*XR+pp+u*4], &xl[c2*XR+pp+u*4], a, b);
        }
    }
    {
        const float* wp = g_w1 + (size_t)blockIdx.y*CC*CC;
        #pragma unroll
        for (int i=0;i<4;i++){
            int idx=tid+i*256; int o=idx>>4, c4=idx&15;
            float4 v=*(const float4*)(wp + o*64 + c4*4);
            uint2 h,l;
            h.x=packbf(v.x,v.y); h.y=packbf(v.z,v.w);
            l.x=packbf(v.x-bfhi(v.x), v.y-bfhi(v.y));
            l.y=packbf(v.z-bfhi(v.z), v.w-bfhi(v.w));
            *(uint2*)&wh[o*WR+2*c4]=h;
            *(uint2*)&wl[o*WR+2*c4]=l;
        }
    }
    __syncthreads();
    int wm=wid&3, wn=wid>>2, g=lane>>2, tg=lane&3;
    float acc[8][4];
    #pragma unroll
    for (int t=0;t<8;t++){ acc[t][0]=0;acc[t][1]=0;acc[t][2]=0;acc[t][3]=0; }
    #pragma unroll
    for (int ks=0;ks<4;ks++){
        int k2=ks*8;
        int r0=(wm*16+g)*WR+k2+tg, r1=(wm*16+8+g)*WR+k2+tg;
        uint32_t Ah[4]={wh[r0],wh[r1],wh[r0+4],wh[r1+4]};
        uint32_t Al[4]={wl[r0],wl[r1],wl[r0+4],wl[r1+4]};
        #pragma unroll
        for (int t=0;t<8;t++){
            int n0=wn*64+t*8+g;
            int i0=(k2+tg)*XR+n0, i1=(k2+4+tg)*XR+n0;
            uint32_t b0h=xh[i0], b1h=xh[i1], b0l=xl[i0], b1l=xl[i1];
            mma16(acc[t],Ah,b0h,b1h);
            mma16(acc[t],Ah,b0l,b1l);
            mma16(acc[t],Al,b0h,b1h);
        }
    }
    float* ob = outp + bbase + nblk;
    #pragma unroll
    for (int t=0;t<8;t++){
        int n0 = wn*64 + t*8 + 2*tg;
        int r0 = wm*16 + g;
        *(float2*)(ob + (size_t)r0*NN + n0)     = make_float2(acc[t][0],acc[t][1]);
        *(float2*)(ob + (size_t)(r0+8)*NN + n0) = make_float2(acc[t][2],acc[t][3]);
    }
}

// =====================================================================
// Precompute M = Wq^T @ Wk for row(0)/col(1), packed bf16 hi/lo
// =====================================================================
__global__ void mprep_k(const float* __restrict__ rq, const float* __restrict__ rk,
                        const float* __restrict__ cq, const float* __restrict__ ck){
    int d = blockIdx.x, tid = threadIdx.x;
    const float* Wq = d ? cq : rq;
    const float* Wk = d ? ck : rk;
    __shared__ float sq[CC*CC], sk[CC*CC], smm[CC*CC];
    for (int i=tid;i<CC*CC;i+=256){ sq[i]=Wq[i]; sk[i]=Wk[i]; }
    __syncthreads();
    for (int e=tid;e<CC*CC;e+=256){
        int a=e>>6, b=e&63;
        float s=0.f;
        #pragma unroll
        for (int c=0;c<CC;c++) s += sq[c*64+a]*sk[c*64+b];
        smm[a*64+b]=s;
    }
    __syncthreads();
    for (int e=tid;e<2048;e+=256){
        int bp=e>>6, a=e&63;
        float v0=smm[a*64+2*bp], v1=smm[a*64+2*bp+1];
        g_mh[d][bp*64+a]=packbf(bfhi(v0),bfhi(v1));
        g_ml[d][bp*64+a]=packbf(v0-bfhi(v0), v1-bfhi(v1));
    }
}

// ---------------- per-batch W1 = att_p_w @ blockdiag(attn) ----------------
__global__ void wcomb1_k(const float* __restrict__ att_p_w){
    int b = blockIdx.x, tid=threadIdx.x;
    __shared__ float sA[NHEADS*32*32];
    __shared__ float sP[CC*CC];
    for (int i=tid;i<NHEADS*32*32;i+=256) sA[i]=g_attn[b*NHEADS*32*32+i];
    for (int i=tid;i<CC*CC;i+=256) sP[i]=att_p_w[i];
    __syncthreads();
    for (int i=tid;i<CC*CC;i+=256){
        int o=i>>6, m=i&63; int g=m>>5, d=m&31;
        float s=0.f;
        #pragma unroll
        for (int c=0;c<32;c++) s += sP[o*64+g*32+c]*sA[g*1024+c*32+d];
        g_w1[(size_t)b*CC*CC + i]=s;
    }
}

// =====================================================================
// Dual-direction fused attention (dir = blockIdx.x >= BB*HH)
// =====================================================================
#define SL 192
#define SSP 204
#define KPR 72
#define VPR 36
#define QR 200
#define FA_SMEM ((SL*SSP + 2*32*QR + 2*32*KPR + SL)*4)   // 227072 B

__global__ __launch_bounds__(256,1)
void fattn_k(const float* __restrict__ X0, const float* __restrict__ X1,
             const uint32_t* __restrict__ mhb, const uint32_t* __restrict__ mlb,
             const float* __restrict__ V0, const float* __restrict__ V1,
             const float* __restrict__ g0p, const float* __restrict__ g1p,
             float* __restrict__ out0, float* __restrict__ out1){
    extern __shared__ float sm[];
    float*    sS = sm;
    uint32_t* qh = (uint32_t*)(sS + SL*SSP);
    uint32_t* ql = qh + 32*QR;
    uint32_t* kvh= ql + 32*QR;
    uint32_t* kvl= kvh + 32*KPR;
    float*    sL = (float*)(kvl + 32*KPR);
    int tid=threadIdx.x, wid=tid>>5, lane=tid&31;
    int dir = blockIdx.x >= BB*HH;
    int bid = blockIdx.x - dir*BB*HH;
    const float* X = dir? X1 : X0;
    const float* V = dir? V1 : V0;
    const float* res = X;
    float* out = dir? out1 : out0;
    const uint32_t* mh = mhb + dir*2048;
    const uint32_t* ml = mlb + dir*2048;
    int b = bid / HH, r = bid % HH;
    size_t base = (size_t)b*CC*NN + (size_t)r*WW;
    {
        int c2=tid>>3, pp=(tid&7)*24;
        const float* r0 = X + base + (size_t)(2*c2)*NN;
        const float* r1 = r0 + NN;
        #pragma unroll
        for (int u=0;u<6;u++){
            float4 a=*(const float4*)(r0+pp+u*4);
            float4 b4=*(const float4*)(r1+pp+u*4);
            stage_pair4(&qh[c2*QR+pp+u*4], &ql[c2*QR+pp+u*4], a, b4);
        }
    }
    __syncthreads();
    int wm = wid&1, wn = wid>>1;
    int g = lane>>2, tg = lane&3;
    float acc[12][4];
    for (int jt=0;jt<3;jt++){
        if (jt) __syncthreads();
        {
            int ymt = wid&3, ywn = wid>>2;
            int jg0 = jt*64 + ymt*16;
            float yac[4][4];
            #pragma unroll
            for (int u=0;u<4;u++){ yac[u][0]=0;yac[u][1]=0;yac[u][2]=0;yac[u][3]=0; }
            #pragma unroll
            for (int kc=0;kc<4;kc++){
                int k2=kc*8;
                uint32_t Ah[4],Al[4];
                Ah[0]=qh[(k2+tg)*QR + jg0+g];   Ah[1]=qh[(k2+tg)*QR + jg0+8+g];
                Ah[2]=qh[(k2+4+tg)*QR + jg0+g]; Ah[3]=qh[(k2+4+tg)*QR + jg0+8+g];
                Al[0]=ql[(k2+tg)*QR + jg0+g];   Al[1]=ql[(k2+tg)*QR + jg0+8+g];
                Al[2]=ql[(k2+4+tg)*QR + jg0+g]; Al[3]=ql[(k2+4+tg)*QR + jg0+8+g];
                #pragma unroll
                for (int u=0;u<4;u++){
                    int n0 = (ywn*4+u)*8;
                    uint32_t b0h = mh[(k2+tg)*64 + n0+g],  b1h = mh[(k2+4+tg)*64 + n0+g];
                    uint32_t b0l = ml[(k2+tg)*64 + n0+g],  b1l = ml[(k2+4+tg)*64 + n0+g];
                    mma16(yac[u],Ah,b0h,b1h);
                    mma16(yac[u],Ah,b0l,b1l);
                    mma16(yac[u],Al,b0h,b1h);
                }
            }
            #pragma unroll
            for (int u=0;u<4;u++){
                int ap = (ywn*4+u)*4 + tg;
                int jl = ymt*16 + g;
                float d0=yac[u][0], d1=yac[u][1], d2=yac[u][2], d3=yac[u][3];
                kvh[ap*KPR + jl]   = packbf(bfhi(d0), bfhi(d1));
                kvl[ap*KPR + jl]   = packbf(d0-bfhi(d0), d1-bfhi(d1));
                kvh[ap*KPR + jl+8] = packbf(bfhi(d2), bfhi(d3));
                kvl[ap*KPR + jl+8] = packbf(d2-bfhi(d2), d3-bfhi(d3));
            }
        }
        __syncthreads();
        #pragma unroll
        for (int t=0;t<12;t++){acc[t][0]=0;acc[t][1]=0;acc[t][2]=0;acc[t][3]=0;}
        #pragma unroll
        for (int kc=0;kc<4;kc++){
            int k2=kc*8;
            uint32_t Ah[2][4], Al[2][4];
            #pragma unroll
            for (int mt=0;mt<2;mt++){
                int m0 = wm*32+mt*16;
                #pragma unroll
                for (int w=0;w<4;w++){
                    int c2p = k2 + tg + (w>>1)*4;
                    int row = m0 + g + (w&1)*8;
                    Ah[mt][w]=kvh[c2p*KPR+row];
                    Al[mt][w]=kvl[c2p*KPR+row];
                }
            }
            #pragma unroll
            for (int nt=0;nt<6;nt++){
                int n0 = wn*48+nt*8+g;
                uint32_t b0h=qh[(k2+tg)*QR+n0],   b1h=qh[(k2+4+tg)*QR+n0];
                uint32_t b0l=ql[(k2+tg)*QR+n0],   b1l=ql[(k2+4+tg)*QR+n0];
                #pragma unroll
                for (int mt=0;mt<2;mt++){
                    float* a = acc[mt*6+nt];
                    mma16(a,Ah[mt],b0h,b1h);
                    mma16(a,Ah[mt],b0l,b1l);
                    mma16(a,Al[mt],b0h,b1h);
                }
            }
        }
        #pragma unroll
        for (int mt=0;mt<2;mt++){
            int j0 = jt*64 + wm*32 + mt*16;
            #pragma unroll
            for (int nt=0;nt<6;nt++){
                int n0 = wn*48+nt*8;
                float* a = acc[mt*6+nt];
                *(float2*)&sS[(j0+g)*SSP + n0+2*tg]   = make_float2(a[0],a[1]);
                *(float2*)&sS[(j0+8+g)*SSP + n0+2*tg] = make_float2(a[2],a[3]);
            }
        }
    }
    __syncthreads();
    if (tid < SL){
        int i = tid;
        float m = -3.4e38f;
        #pragma unroll 8
        for (int j=0;j<SL;j++) m = fmaxf(m, sS[j*SSP+i]);
        float s = 0.f;
        #pragma unroll 4
        for (int j2=0;j2<SL/2;j2++){
            float e0 = __expf(sS[(2*j2)*SSP+i]-m);
            float e1 = __expf(sS[(2*j2+1)*SSP+i]-m);
            s += e0+e1;
            sS[(2*j2)*SSP+i]   = __uint_as_float(packbf(e0,e1));
            sS[(2*j2+1)*SSP+i] = __uint_as_float(packbf(e0-bfhi(e0), e1-bfhi(e1)));
        }
        sL[i] = 1.f/s;
    }
    #pragma unroll
    for (int t=0;t<12;t++){acc[t][0]=0;acc[t][1]=0;acc[t][2]=0;acc[t][3]=0;}
    for (int jt=0;jt<3;jt++){
        __syncthreads();
        {
            int c = tid>>2, j20 = (tid&3)*8;
            const float4* src = (const float4*)(V + base + (size_t)c*NN + jt*64 + j20*2);
            #pragma unroll
            for (int u=0;u<4;u++){
                float4 v = src[u];
                uint2 h,l;
                h.x=packbf(v.x,v.y); h.y=packbf(v.z,v.w);
                l.x=packbf(v.x-bfhi(v.x), v.y-bfhi(v.y));
                l.y=packbf(v.z-bfhi(v.z), v.w-bfhi(v.w));
                *(uint2*)&kvh[c*VPR + j20 + 2*u] = h;
                *(uint2*)&kvl[c*VPR + j20 + 2*u] = l;
            }
        }
        __syncthreads();
        #pragma unroll
        for (int kc=0;kc<4;kc++){
            uint32_t Ah[2][4], Al[2][4];
            #pragma unroll
            for (int mt=0;mt<2;mt++){
                int m0 = wm*32+mt*16;
                #pragma unroll
                for (int w=0;w<4;w++){
                    int row = m0 + g + (w&1)*8;
                    int jp  = kc*8 + tg + (w>>1)*4;
                    Ah[mt][w]=kvh[row*VPR+jp];
                    Al[mt][w]=kvl[row*VPR+jp];
                }
            }
            int j2g = jt*32 + kc*8;
            #pragma unroll
            for (int nt=0;nt<6;nt++){
                int n0 = wn*48+nt*8+g;
                uint32_t b0h=__float_as_uint(sS[(2*(j2g+tg))*SSP+n0]);
                uint32_t b0l=__float_as_uint(sS[(2*(j2g+tg)+1)*SSP+n0]);
                uint32_t b1h=__float_as_uint(sS[(2*(j2g+4+tg))*SSP+n0]);
                uint32_t b1l=__float_as_uint(sS[(2*(j2g+4+tg)+1)*SSP+n0]);
                #pragma unroll
                for (int mt=0;mt<2;mt++){
                    float* a = acc[mt*6+nt];
                    mma16(a,Ah[mt],b0h,b1h);
                    mma16(a,Ah[mt],b0l,b1l);
                    mma16(a,Al[mt],b0h,b1h);
                }
            }
        }
    }
    float gm = dir? g1p[0] : g0p[0];
    #pragma unroll
    for (int mt=0;mt<2;mt++){
        int m0 = wm*32+mt*16;
        #pragma unroll
        for (int nt=0;nt<6;nt++){
            int n0 = wn*48+nt*8 + 2*tg;
            float il0 = sL[n0], il1 = sL[n0+1];
            float* a = acc[mt*6+nt];
            float2 r0 = *(const float2*)(res + base + (size_t)(m0+g)*NN + n0);
            float2 r1 = *(const float2*)(res + base + (size_t)(m0+8+g)*NN + n0);
            *(float2*)(out + base + (size_t)(m0+g)*NN + n0) =
                make_float2(gm*a[0]*il0 + r0.x, gm*a[1]*il1 + r0.y);
            *(float2*)(out + base + (size_t)(m0+8+g)*NN + n0) =
                make_float2(gm*a[2]*il0 + r1.x, gm*a[3]*il1 + r1.y);
        }
    }
}

// ---------------- depthwise 3x3: column-owned staging, no div/mod ----------------
#define DWROWS 8
__global__ __launch_bounds__(192)
void dwconv_k(const float* __restrict__ in, const float* __restrict__ w,
              const float* __restrict__ bias, float* __restrict__ out){
    __shared__ float sm[(DWROWS+2)*194];
    int bc = blockIdx.y;
    int y0 = blockIdx.x*DWROWS;
    int c  = bc & (CC-1);
    const float* ip = in + (size_t)bc*NN;
    float* op = out + (size_t)bc*NN;
    int x = threadIdx.x;
    float wr[9];
    #pragma unroll
    for (int i=0;i<9;i++) wr[i]=w[c*9+i];
    float bv = bias[c];
    // thread x owns smem column x (gx = x-1); x<2 also fills cols 192/193
    #pragma unroll
    for (int row=0; row<DWROWS+2; row++){
        int gy = y0 + row - 1;
        bool yok = (unsigned)gy < HH;
        float v = (yok && x>0) ? ip[(size_t)gy*WW + (x-1)] : 0.f;
        sm[row*194 + x] = v;
        if (x < 2){
            float v2 = (yok && x==0) ? ip[(size_t)gy*WW + 191] : 0.f;
            sm[row*194 + 192 + x] = v2;
        }
    }
    __syncthreads();
    #pragma unroll
    for (int r=0;r<DWROWS;r++){
        const float* s0=&sm[(r+0)*194 + x];
        const float* s1=&sm[(r+1)*194 + x];
        const float* s2=&sm[(r+2)*194 + x];
        float acc = bv
            + wr[0]*s0[0] + wr[1]*s0[1] + wr[2]*s0[2]
            + wr[3]*s1[0] + wr[4]*s1[1] + wr[5]*s1[2]
            + wr[6]*s2[0] + wr[7]*s2[1] + wr[8]*s2[2];
        op[(size_t)(y0+r)*WW + x] = gelu_f(acc);
    }
}

// ---------------- transposes ----------------
__global__ void transpose_k(const float* __restrict__ in, float* __restrict__ out){
    __shared__ float t[32][33];
    const float* ib = in + (size_t)blockIdx.z*NN;
    float* ob = out + (size_t)blockIdx.z*NN;
    int x = blockIdx.x*32 + threadIdx.x;
    #pragma unroll
    for (int k=0;k<32;k+=8)
        t[threadIdx.y+k][threadIdx.x] = ib[(size_t)(blockIdx.y*32+threadIdx.y+k)*WW + x];
    __syncthreads();
    int x2 = blockIdx.y*32 + threadIdx.x;
    #pragma unroll
    for (int k=0;k<32;k+=8)
        ob[(size_t)(blockIdx.x*32+threadIdx.y+k)*HH + x2] = t[threadIdx.x][threadIdx.y+k];
}

__global__ void transpose2_k(const float* __restrict__ in0, float* __restrict__ out0,
                             const float* __restrict__ in1, float* __restrict__ out1){
    __shared__ float t[32][33];
    int z = blockIdx.z;
    int sel = z >= BB*CC;
    int zz = sel ? z - BB*CC : z;
    const float* ib = (sel? in1 : in0) + (size_t)zz*NN;
    float* ob = (sel? out1: out0) + (size_t)zz*NN;
    int x = blockIdx.x*32 + threadIdx.x;
    #pragma unroll
    for (int k=0;k<32;k+=8)
        t[threadIdx.y+k][threadIdx.x] = ib[(size_t)(blockIdx.y*32+threadIdx.y+k)*WW + x];
    __syncthreads();
    int x2 = blockIdx.y*32 + threadIdx.x;
    #pragma unroll
    for (int k=0;k<32;k+=8)
        ob[(size_t)(blockIdx.x*32+threadIdx.y+k)*HH + x2] = t[threadIdx.x][threadIdx.y+k];
}

__global__ void zero_attn_k(){
    int i = blockIdx.x*blockDim.x+threadIdx.x;
    if (i < BB*NHEADS*32*32) g_attn[i]=0.f;
    if (i < 2*BB*CC) g_norm[i]=0.f;
}

// ---------------- channel-attn gram (chunked atomics) + fused q/k norms ----------------
#define NCHUNK 32
#define CHUNK (NN/NCHUNK)
__global__ void gram_k(const float* __restrict__ q, const float* __restrict__ k){
    int bg = blockIdx.x; int b=bg/NHEADS, g=bg%NHEADS;
    int n0 = blockIdx.y*CHUNK;
    __shared__ float qs[64][33], ks[64][33];
    int c = threadIdx.x>>3, dg = threadIdx.x&7;
    float a0=0,a1=0,a2=0,a3=0;
    float nq=0.f, nk0=0.f, nk1=0.f, nk2=0.f, nk3=0.f;
    const float* qb = q + ((size_t)(b*CC + g*32))*NN + n0;
    const float* kb = k + ((size_t)(b*CC + g*32))*NN + n0;
    for (int tt=0;tt<CHUNK;tt+=64){
        __syncthreads();
        for (int e=threadIdx.x;e<32*64;e+=256){
            int cc=e>>6, t=e&63;
            qs[t][cc]=qb[(size_t)cc*NN + tt + t];
            ks[t][cc]=kb[(size_t)cc*NN + tt + t];
        }
        __syncthreads();
        #pragma unroll 8
        for (int t=0;t<64;t++){
            float qv=qs[t][c];
            float k0=ks[t][dg], k1=ks[t][dg+8], k2=ks[t][dg+16], k3=ks[t][dg+24];
            a0+=qv*k0; a1+=qv*k1; a2+=qv*k2; a3+=qv*k3;
            if (dg==0) nq += qv*qv;
            if (c==0){ nk0+=k0*k0; nk1+=k1*k1; nk2+=k2*k2; nk3+=k3*k3; }
        }
    }
    float* ab = g_attn + ((size_t)(bg*32+c))*32;
    atomicAdd(&ab[dg],a0);    atomicAdd(&ab[dg+8],a1);
    atomicAdd(&ab[dg+16],a2); atomicAdd(&ab[dg+24],a3);
    if (dg==0) atomicAdd(&g_norm[b*CC + g*32 + c], nq);
    if (c==0){
        float* nb = g_norm + BB*CC + b*CC + g*32;
        atomicAdd(&nb[dg],nk0);    atomicAdd(&nb[dg+8],nk1);
        atomicAdd(&nb[dg+16],nk2); atomicAdd(&nb[dg+24],nk3);
    }
}

// ---------------- channel-attn softmax ----------------
__global__ void chsm_k(const float* __restrict__ temp){
    int bg = blockIdx.x; int b=bg/NHEADS, g=bg%NHEADS;
    int c = threadIdx.x>>5, d = threadIdx.x&31;
    float nq = fmaxf(sqrtf(g_norm[b*CC + g*32 + c]), 1e-12f);
    float nk = fmaxf(sqrtf(g_norm[BB*CC + b*CC + g*32 + d]), 1e-12f);
    int idx = (bg*32+c)*32+d;
    float v = g_attn[idx]/(nq*nk)*temp[g];
    float m=v;
    #pragma unroll
    for (int o=16;o;o>>=1) m=fmaxf(m,__shfl_xor_sync(0xffffffffu,m,o));
    float e=expf(v-m), s=e;
    #pragma unroll
    for (int o=16;o;o>>=1) s+=__shfl_xor_sync(0xffffffffu,s,o);
    g_attn[idx]=e/s;
}

// =======================================================================
extern "C" void kernel_launch(void* const* d_in, const int* in_sizes, int n_in,
                              void* d_out, int out_size){
    const float* x      =(const float*)d_in[0];
    const float* pw_w   =(const float*)d_in[1];
    const float* dw_w   =(const float*)d_in[2];
    const float* dw_b   =(const float*)d_in[3];
    const float* conv2_w=(const float*)d_in[4];
    const float* conv2_b=(const float*)d_in[5];
    const float* conv0_w=(const float*)d_in[6];
    const float* conv0_b=(const float*)d_in[7];
    const float* att_q_w=(const float*)d_in[8];
    const float* att_k_w=(const float*)d_in[9];
    const float* att_v_w=(const float*)d_in[10];
    const float* att_p_w=(const float*)d_in[11];
    const float* temp   =(const float*)d_in[12];
    const float* row_q_w=(const float*)d_in[13];
    const float* row_k_w=(const float*)d_in[14];
    const float* row_v_w=(const float*)d_in[15];
    const float* row_g  =(const float*)d_in[16];
    const float* col_q_w=(const float*)d_in[17];
    const float* col_k_w=(const float*)d_in[18];
    const float* col_v_w=(const float*)d_in[19];
    const float* col_g  =(const float*)d_in[20];
    const float* conv_w =(const float*)d_in[21];
    const float* conv_b =(const float*)d_in[22];
    float* out=(float*)d_out;

    float *t0,*t1,*x1b,*q,*k,*v,*o1,*o2,*o3;
    uint32_t *mh,*ml;
    cudaGetSymbolAddress((void**)&t0,  g_t0);
    cudaGetSymbolAddress((void**)&t1,  g_t1);
    cudaGetSymbolAddress((void**)&x1b, g_x1);
    cudaGetSymbolAddress((void**)&q,   g_q);
    cudaGetSymbolAddress((void**)&k,   g_k);
    cudaGetSymbolAddress((void**)&v,   g_v);
    cudaGetSymbolAddress((void**)&o1,  g_o1);
    cudaGetSymbolAddress((void**)&o2,  g_o2);
    cudaGetSymbolAddress((void**)&o3,  g_o3);
    cudaGetSymbolAddress((void**)&mh,  g_mh);
    cudaGetSymbolAddress((void**)&ml,  g_ml);

    const int SM_Q1 = (2*XW_WORDS + 1*2*WW_WORDS)*4;   // 53248
    const int SM_Q2 = (2*XW_WORDS + 2*2*WW_WORDS)*4;   // 71680
    const int SM_Q3 = (2*XW_WORDS + 3*2*WW_WORDS)*4;   // 90112
    const int SM_CM = (2*XW_WORDS + 2*WW_WORDS)*4;     // 53248
    cudaFuncSetAttribute(qkvmma_k<1>, cudaFuncAttributeMaxDynamicSharedMemorySize, SM_Q1);
    cudaFuncSetAttribute(qkvmma_k<2>, cudaFuncAttributeMaxDynamicSharedMemorySize, SM_Q2);
    cudaFuncSetAttribute(qkvmma_k<3>, cudaFuncAttributeMaxDynamicSharedMemorySize, SM_Q3);
    cudaFuncSetAttribute(cmma_k<2,2,false>, cudaFuncAttributeMaxDynamicSharedMemorySize, SM_CM);
    cudaFuncSetAttribute(cmma_k<3,1,true>,  cudaFuncAttributeMaxDynamicSharedMemorySize, SM_CM);
    cudaFuncSetAttribute(cmma_pb_k, cudaFuncAttributeMaxDynamicSharedMemorySize, SM_CM);
    cudaFuncSetAttribute(fattn_k, cudaFuncAttributeMaxDynamicSharedMemorySize, FA_SMEM);

    dim3 mg(NN/128, BB);

    // ---- prologue ----
    zero_attn_k<<<32,256>>>();
    mprep_k<<<2,256>>>(row_q_w,row_k_w,col_q_w,col_k_w);

    // ---- BSConvU + skip -> x1 ----
    qkvmma_k<1><<<mg,256,SM_Q1>>>(x, pw_w,nullptr,nullptr, t0,nullptr,nullptr);
    dwconv_k<<<dim3(HH/DWROWS, BB*CC),192>>>(t0, dw_w, dw_b, t1);
    cmma_k<2,2,false><<<mg,256,SM_CM>>>(t1,x,nullptr, conv2_w,conv0_w,nullptr, 64,
                                        conv2_b,conv0_b, x1b);

    // ---- channel self-attention: qkv, gram(+norm), softmax, W1-fold, o1 ----
    qkvmma_k<3><<<mg,256,SM_Q3>>>(x1b, att_q_w,att_k_w,att_v_w, q,k,v);
    gram_k<<<dim3(BB*NHEADS,NCHUNK),256>>>(q,k);
    chsm_k<<<BB*NHEADS,1024>>>(temp);
    wcomb1_k<<<BB,256>>>(att_p_w);
    cmma_pb_k<<<mg,256,SM_CM>>>(v, o1);

    // ---- row V + col V in one conv of o1; transposes batched ----
    qkvmma_k<2><<<mg,256,SM_Q2>>>(o1, row_v_w,col_v_w,nullptr, v, t0, nullptr);
    transpose2_k<<<dim3(6,6,2*BB*CC),dim3(32,8)>>>(x1b, t1, t0, k);   // t1=x1^T, k=colV^T

    // ---- both attention directions in ONE launch ----
    fattn_k<<<2*BB*HH,256,FA_SMEM>>>(x1b, t1, mh, ml, v, k, row_g, col_g, o2, q);
    transpose_k<<<dim3(6,6,BB*CC),dim3(32,8)>>>(q, o3);

    // ---- fuse ----
    cmma_k<3,1,true><<<mg,256,SM_CM>>>(o1,o2,o3, conv_w,conv_w+64,conv_w+128, 192,
                                       conv_b,nullptr, out);
}